// round 1
// baseline (speedup 1.0000x reference)
#include <cuda_runtime.h>
#include <math_constants.h>

#define B_  2
#define S_  2048
#define D_  1024
#define H_  16
#define HD_ 64

// Scratch (allocation-free rule: __device__ globals)
__device__ float g_q[B_*S_*D_];
__device__ float g_k[B_*S_*D_];
__device__ float g_v[B_*S_*D_];
__device__ float g_y[B_*S_*D_];

// ---------------------------------------------------------------------------
// GEMM: C[M,N] = A[M,K] @ B[N,K]^T   (M=4096 or per-grid, N=K=1024 fixed)
// 128x128 block tile, BK=16, 256 threads, 8x8 register tile per thread.
// ---------------------------------------------------------------------------
__device__ __forceinline__ void gemm128_body(const float* __restrict__ A,
                                             const float* __restrict__ Bm,
                                             float* __restrict__ C) {
    __shared__ __align__(16) float As[16][132];
    __shared__ __align__(16) float Bs[16][132];
    const int tid = threadIdx.x;
    const int tx = tid & 15, ty = tid >> 4;
    const int m0 = blockIdx.y * 128;
    const int n0 = blockIdx.x * 128;

    float acc[8][8];
#pragma unroll
    for (int i = 0; i < 8; i++)
#pragma unroll
        for (int j = 0; j < 8; j++) acc[i][j] = 0.f;

    for (int k0 = 0; k0 < 1024; k0 += 16) {
        __syncthreads();
#pragma unroll
        for (int q = 0; q < 2; q++) {
            int l  = q * 256 + tid;
            int r  = l >> 2;            // 0..127 (tile row)
            int kk = (l & 3) * 4;       // 0,4,8,12
            float4 av = *(const float4*)(A  + (size_t)(m0 + r) * 1024 + k0 + kk);
            As[kk+0][r] = av.x; As[kk+1][r] = av.y; As[kk+2][r] = av.z; As[kk+3][r] = av.w;
            float4 bv = *(const float4*)(Bm + (size_t)(n0 + r) * 1024 + k0 + kk);
            Bs[kk+0][r] = bv.x; Bs[kk+1][r] = bv.y; Bs[kk+2][r] = bv.z; Bs[kk+3][r] = bv.w;
        }
        __syncthreads();
#pragma unroll
        for (int k = 0; k < 16; k++) {
            float a[8], b[8];
            *(float4*)(a)     = *(const float4*)&As[k][ty*8];
            *(float4*)(a + 4) = *(const float4*)&As[k][ty*8 + 4];
            *(float4*)(b)     = *(const float4*)&Bs[k][tx*8];
            *(float4*)(b + 4) = *(const float4*)&Bs[k][tx*8 + 4];
#pragma unroll
            for (int i = 0; i < 8; i++)
#pragma unroll
                for (int j = 0; j < 8; j++)
                    acc[i][j] = fmaf(a[i], b[j], acc[i][j]);
        }
    }

#pragma unroll
    for (int i = 0; i < 8; i++) {
        float* cp = C + (size_t)(m0 + ty*8 + i) * 1024 + n0 + tx*8;
        *(float4*)(cp)     = make_float4(acc[i][0], acc[i][1], acc[i][2], acc[i][3]);
        *(float4*)(cp + 4) = make_float4(acc[i][4], acc[i][5], acc[i][6], acc[i][7]);
    }
}

__global__ void qkv_gemm_kernel(const float* __restrict__ x,
                                const float* __restrict__ Wq,
                                const float* __restrict__ Wk,
                                const float* __restrict__ Wv) {
    const float* W = (blockIdx.z == 0) ? Wq : (blockIdx.z == 1) ? Wk : Wv;
    float*       C = (blockIdx.z == 0) ? g_q : (blockIdx.z == 1) ? g_k : g_v;
    gemm128_body(x, W, C);
}

__global__ void out_gemm_kernel(const float* __restrict__ Wo,
                                float* __restrict__ out) {
    gemm128_body(g_y, Wo, out);
}

// ---------------------------------------------------------------------------
// RoPE (in-place on g_q / g_k). One thread per (tensor,row,pair).
// ---------------------------------------------------------------------------
__global__ void rope_kernel(const int* __restrict__ tok,
                            const int* __restrict__ use_rope,
                            const float* __restrict__ cs,
                            const float* __restrict__ sn) {
    if (use_rope[0] == 0) return;
    int idx = blockIdx.x * blockDim.x + threadIdx.x;     // 0 .. 2*4096*512-1
    int t   = idx >> 21;                                  // 0:q 1:k
    int rp  = idx & ((1 << 21) - 1);
    int row = rp >> 9;                                    // 0..4095
    int pp  = rp & 511;                                   // pair within row
    int h   = pp >> 5, j = pp & 31;
    int s   = row & (S_ - 1);
    int pos = tok[s];
    float c  = cs[pos * 32 + j];
    float si = sn[pos * 32 + j];
    float* T = t ? g_k : g_q;
    float2* p = (float2*)(T + (size_t)row * D_ + h * HD_ + 2 * j);
    float2 v = *p;
    *p = make_float2(v.x * c - v.y * si, v.y * c + v.x * si);
}

// ---------------------------------------------------------------------------
// Flash attention, fp32, causal. Br=Bc=64, d=64. 256 threads (16x16),
// 4x4 micro-tile. K stored transposed in smem; P aliases the K buffer.
// ---------------------------------------------------------------------------
__global__ void flash_kernel() {
    __shared__ __align__(16) float Qs [64][64];
    __shared__ __align__(16) float Kst[64][64];   // reused as P after S
    __shared__ __align__(16) float Vs [64][64];

    const int tid = threadIdx.x;
    const int tx = tid & 15, ty = tid >> 4;
    const int qt = blockIdx.x, h = blockIdx.y, b = blockIdx.z;
    const int q0 = qt * 64;
    const size_t baseQ = ((size_t)(b * S_) + q0) * D_ + h * HD_;

#pragma unroll
    for (int q = 0; q < 4; q++) {
        int l = q * 256 + tid;
        int r = l >> 4, c4 = (l & 15) * 4;
        *(float4*)&Qs[r][c4] = *(const float4*)(g_q + baseQ + (size_t)r * D_ + c4);
    }

    float m_i[4], l_i[4], o[4][4];
#pragma unroll
    for (int i = 0; i < 4; i++) {
        m_i[i] = -CUDART_INF_F; l_i[i] = 0.f;
#pragma unroll
        for (int j = 0; j < 4; j++) o[i][j] = 0.f;
    }

    for (int kt = 0; kt <= qt; kt++) {
        __syncthreads();  // protects Kst/Vs reuse across iterations (and Qs on iter 0)
        const size_t baseK = ((size_t)(b * S_) + kt * 64) * D_ + h * HD_;
#pragma unroll
        for (int q = 0; q < 4; q++) {
            int l = q * 256 + tid;
            int r = l >> 4, c4 = (l & 15) * 4;
            float4 kv = *(const float4*)(g_k + baseK + (size_t)r * D_ + c4);
            Kst[c4+0][r] = kv.x; Kst[c4+1][r] = kv.y; Kst[c4+2][r] = kv.z; Kst[c4+3][r] = kv.w;
            *(float4*)&Vs[r][c4] = *(const float4*)(g_v + baseK + (size_t)r * D_ + c4);
        }
        __syncthreads();

        // S = Q @ K^T
        float s[4][4];
#pragma unroll
        for (int i = 0; i < 4; i++)
#pragma unroll
            for (int j = 0; j < 4; j++) s[i][j] = 0.f;

#pragma unroll 16
        for (int d = 0; d < 64; d++) {
            float kf[4];
            *(float4*)kf = *(const float4*)&Kst[d][tx*4];
#pragma unroll
            for (int i = 0; i < 4; i++) {
                float qv = Qs[ty*4 + i][d];
#pragma unroll
                for (int j = 0; j < 4; j++)
                    s[i][j] = fmaf(qv, kf[j], s[i][j]);
            }
        }

        // scale + causal mask + row max
        const float scale = 0.125f;
        const int rowg = q0 + ty * 4, colg = kt * 64 + tx * 4;
        float mt[4];
#pragma unroll
        for (int i = 0; i < 4; i++) {
            mt[i] = -CUDART_INF_F;
#pragma unroll
            for (int j = 0; j < 4; j++) {
                float sv = s[i][j] * scale;
                if (colg + j > rowg + i) sv = -CUDART_INF_F;
                s[i][j] = sv;
                mt[i] = fmaxf(mt[i], sv);
            }
        }
#pragma unroll
        for (int off = 8; off > 0; off >>= 1)
#pragma unroll
            for (int i = 0; i < 4; i++)
                mt[i] = fmaxf(mt[i], __shfl_xor_sync(0xffffffffu, mt[i], off));

        // online softmax update
        float pt[4];
#pragma unroll
        for (int i = 0; i < 4; i++) {
            float mn = fmaxf(m_i[i], mt[i]);
            float alpha = __expf(m_i[i] - mn);
            m_i[i] = mn;
            pt[i] = 0.f;
#pragma unroll
            for (int j = 0; j < 4; j++) {
                s[i][j] = __expf(s[i][j] - mn);
                pt[i] += s[i][j];
            }
#pragma unroll
            for (int j = 0; j < 4; j++) o[i][j] *= alpha;
            l_i[i] *= alpha;
        }
#pragma unroll
        for (int off = 8; off > 0; off >>= 1)
#pragma unroll
            for (int i = 0; i < 4; i++)
                pt[i] += __shfl_xor_sync(0xffffffffu, pt[i], off);
#pragma unroll
        for (int i = 0; i < 4; i++) l_i[i] += pt[i];

        __syncthreads();  // everyone done reading Kst before P overwrite
#pragma unroll
        for (int i = 0; i < 4; i++)
#pragma unroll
            for (int j = 0; j < 4; j++)
                Kst[ty*4 + i][tx*4 + j] = s[i][j];   // P tile
        __syncthreads();

        // O += P @ V
#pragma unroll 16
        for (int c = 0; c < 64; c++) {
            float vf[4];
            *(float4*)vf = *(const float4*)&Vs[c][tx*4];
#pragma unroll
            for (int i = 0; i < 4; i++) {
                float pv = Kst[ty*4 + i][c];
#pragma unroll
                for (int j = 0; j < 4; j++)
                    o[i][j] = fmaf(pv, vf[j], o[i][j]);
            }
        }
    }

    // epilogue: O / l, write to g_y
#pragma unroll
    for (int i = 0; i < 4; i++) {
        float inv = 1.f / l_i[i];
        float4 ov = make_float4(o[i][0]*inv, o[i][1]*inv, o[i][2]*inv, o[i][3]*inv);
        *(float4*)(g_y + baseQ + (size_t)(ty*4 + i) * D_ + tx*4) = ov;
    }
}

// ---------------------------------------------------------------------------
extern "C" void kernel_launch(void* const* d_in, const int* in_sizes, int n_in,
                              void* d_out, int out_size) {
    const float* x        = (const float*)d_in[0];
    const int*   tok      = (const int*)  d_in[1];
    const int*   use_rope = (const int*)  d_in[2];
    const float* Wq       = (const float*)d_in[3];
    const float* Wk       = (const float*)d_in[4];
    const float* Wv       = (const float*)d_in[5];
    const float* Wo       = (const float*)d_in[6];
    const float* cs       = (const float*)d_in[7];
    const float* sn       = (const float*)d_in[8];
    float* out = (float*)d_out;

    qkv_gemm_kernel<<<dim3(8, 32, 3), 256>>>(x, Wq, Wk, Wv);
    rope_kernel<<<(2u * B_ * S_ * (D_ / 2)) / 256u, 256>>>(tok, use_rope, cs, sn);
    flash_kernel<<<dim3(S_ / 64, H_, B_), 256>>>();
    out_gemm_kernel<<<dim3(8, 32), 256>>>(Wo, out);
}

// round 3
// speedup vs baseline: 1.4049x; 1.4049x over previous
#include <cuda_runtime.h>
#include <cuda_bf16.h>
#include <math_constants.h>
#include <cstdint>

#define B_  2
#define S_  2048
#define D_  1024
#define H_  16
#define HD_ 64

// ---------------------------------------------------------------------------
// Scratch (__device__ globals; allocation-free rule)
// ---------------------------------------------------------------------------
__device__ float g_q[B_*S_*D_];
__device__ float g_k[B_*S_*D_];
__device__ float g_v[B_*S_*D_];
__device__ float g_y[B_*S_*D_];

__device__ __align__(16) __nv_bfloat16 g_xhi[B_*S_*D_], g_xlo[B_*S_*D_];
__device__ __align__(16) __nv_bfloat16 g_yhi[B_*S_*D_], g_ylo[B_*S_*D_];
__device__ __align__(16) __nv_bfloat16 g_wqhi[D_*D_], g_wqlo[D_*D_];
__device__ __align__(16) __nv_bfloat16 g_wkhi[D_*D_], g_wklo[D_*D_];
__device__ __align__(16) __nv_bfloat16 g_wvhi[D_*D_], g_wvlo[D_*D_];
__device__ __align__(16) __nv_bfloat16 g_wohi[D_*D_], g_wolo[D_*D_];

// ---------------------------------------------------------------------------
// Low-level helpers (base-target instructions only: sm_80 class)
// ---------------------------------------------------------------------------
__device__ __forceinline__ uint32_t smem_to_u32(const void* p) {
    uint32_t a;
    asm("{ .reg .u64 t; cvta.to.shared.u64 t, %1; cvt.u32.u64 %0, t; }" : "=r"(a) : "l"(p));
    return a;
}

__device__ __forceinline__ void cp16(uint32_t saddr, const void* gaddr) {
    asm volatile("cp.async.cg.shared.global [%0], [%1], 16;" :: "r"(saddr), "l"(gaddr));
}
#define CP_COMMIT() asm volatile("cp.async.commit_group;" ::: "memory")
#define CP_WAIT1()  asm volatile("cp.async.wait_group 1;"  ::: "memory")

__device__ __forceinline__ void ldmx4(uint32_t* r, uint32_t addr) {
    asm volatile("ldmatrix.sync.aligned.m8n8.x4.shared.b16 {%0,%1,%2,%3}, [%4];"
        : "=r"(r[0]), "=r"(r[1]), "=r"(r[2]), "=r"(r[3]) : "r"(addr));
}

__device__ __forceinline__ void mma16816(float* c, const uint32_t* a, const uint32_t* b) {
    asm volatile(
        "mma.sync.aligned.m16n8k16.row.col.f32.bf16.bf16.f32 "
        "{%0,%1,%2,%3}, {%4,%5,%6,%7}, {%8,%9}, {%0,%1,%2,%3};"
        : "+f"(c[0]), "+f"(c[1]), "+f"(c[2]), "+f"(c[3])
        : "r"(a[0]), "r"(a[1]), "r"(a[2]), "r"(a[3]), "r"(b[0]), "r"(b[1]));
}

// ---------------------------------------------------------------------------
// Split fp32 -> (hi, lo) bf16
// ---------------------------------------------------------------------------
__global__ void split_kernel(const float* __restrict__ src,
                             __nv_bfloat16* __restrict__ hi,
                             __nv_bfloat16* __restrict__ lo, int n4) {
    int i = blockIdx.x * blockDim.x + threadIdx.x;
    if (i >= n4) return;
    float4 v = ((const float4*)src)[i];
    float vv[4] = {v.x, v.y, v.z, v.w};
    unsigned short hs[4], ls[4];
#pragma unroll
    for (int j = 0; j < 4; j++) {
        __nv_bfloat16 hb = __float2bfloat16(vv[j]);
        float r = vv[j] - __bfloat162float(hb);
        __nv_bfloat16 lb = __float2bfloat16(r);
        hs[j] = __bfloat16_as_ushort(hb);
        ls[j] = __bfloat16_as_ushort(lb);
    }
    ((ushort4*)hi)[i] = make_ushort4(hs[0], hs[1], hs[2], hs[3]);
    ((ushort4*)lo)[i] = make_ushort4(ls[0], ls[1], ls[2], ls[3]);
}

// ---------------------------------------------------------------------------
// mma.sync bf16 split GEMM: C[M,N] = A[M,K] @ B[N,K]^T, K=N=1024.
// 128x128 CTA tile, BK=32, 256 threads (8 warps 2x4), warp tile 64x32.
// cp.async double-buffered smem; hi/lo bf16 3-pass for fp32-class accuracy.
// ---------------------------------------------------------------------------
#define BK     32
#define PAD    40                       // bf16 elems per smem row (80 B)
#define TILE_B (128 * PAD * 2)          // 10240 B per tile
#define STAGE_B (4 * TILE_B)            // Ahi,Alo,Bhi,Blo = 40960 B
#define GEMM_SMEM (2 * STAGE_B)         // 81920 B

__device__ __forceinline__ void load_stage(uint32_t sb, int stg, int kc,
        const __nv_bfloat16* __restrict__ Ahi, const __nv_bfloat16* __restrict__ Alo,
        const __nv_bfloat16* __restrict__ Bhi, const __nv_bfloat16* __restrict__ Blo,
        int m0, int n0, int tid) {
    const __nv_bfloat16* srcs[4] = {Ahi, Alo, Bhi, Blo};
    const int r0s[4] = {m0, m0, n0, n0};
    uint32_t base = sb + stg * STAGE_B;
#pragma unroll
    for (int t = 0; t < 4; t++) {
        const __nv_bfloat16* src = srcs[t];
        const int r0 = r0s[t];
        uint32_t tb = base + t * TILE_B;
#pragma unroll
        for (int it = 0; it < 2; it++) {
            int seg = it * 256 + tid;
            int r = seg >> 2, c8 = (seg & 3) * 8;
            cp16(tb + (r * PAD + c8) * 2,
                 src + (size_t)(r0 + r) * 1024 + kc * BK + c8);
        }
    }
}

__device__ __forceinline__ void tc_gemm_body(
        const __nv_bfloat16* __restrict__ Ahi, const __nv_bfloat16* __restrict__ Alo,
        const __nv_bfloat16* __restrict__ Bhi, const __nv_bfloat16* __restrict__ Blo,
        float* __restrict__ C) {
    extern __shared__ char smem[];
    const uint32_t sb = smem_to_u32(smem);
    const int tid = threadIdx.x, lane = tid & 31, warp = tid >> 5;
    const int wm = warp >> 2, wn = warp & 3;       // 2 x 4 warp grid
    const int m0 = blockIdx.y * 128, n0 = blockIdx.x * 128;

    float acc[4][4][4];
#pragma unroll
    for (int i = 0; i < 4; i++)
#pragma unroll
        for (int j = 0; j < 4; j++)
#pragma unroll
            for (int e = 0; e < 4; e++) acc[i][j][e] = 0.f;

    load_stage(sb, 0, 0, Ahi, Alo, Bhi, Blo, m0, n0, tid);
    CP_COMMIT();
    load_stage(sb, 1, 1, Ahi, Alo, Bhi, Blo, m0, n0, tid);
    CP_COMMIT();

    // ldmatrix address components (constant across chunks)
    const int a_row = lane & 15;                       // + (lane>>4)*8 in col
    const int a_coff = (lane >> 4) * 8;
    const int b_row = (lane & 7) + ((lane >> 4) << 3); // lanes 16-31 -> +8 rows
    const int b_coff = ((lane >> 3) & 1) * 8;

    for (int kc = 0; kc < 1024 / BK; kc++) {
        CP_WAIT1();
        __syncthreads();
        const int stg = kc & 1;
        const uint32_t aHiB = sb + stg * STAGE_B;
        const uint32_t aLoB = aHiB + TILE_B;
        const uint32_t bHiB = aLoB + TILE_B;
        const uint32_t bLoB = bHiB + TILE_B;

#pragma unroll
        for (int ks = 0; ks < 2; ks++) {
            const int k0 = ks * 16;
            uint32_t ahi[4][4], alo[4][4];
#pragma unroll
            for (int mt = 0; mt < 4; mt++) {
                uint32_t off = (uint32_t)(((wm * 64 + mt * 16 + a_row) * PAD + k0 + a_coff) * 2);
                ldmx4(ahi[mt], aHiB + off);
                ldmx4(alo[mt], aLoB + off);
            }
            uint32_t bhi[2][4], blo[2][4];
#pragma unroll
            for (int nt2 = 0; nt2 < 2; nt2++) {
                uint32_t off = (uint32_t)(((wn * 32 + nt2 * 16 + b_row) * PAD + k0 + b_coff) * 2);
                ldmx4(bhi[nt2], bHiB + off);
                ldmx4(blo[nt2], bLoB + off);
            }
#pragma unroll
            for (int mt = 0; mt < 4; mt++)
#pragma unroll
                for (int nt = 0; nt < 4; nt++) {
                    const uint32_t* bh = &bhi[nt >> 1][(nt & 1) * 2];
                    const uint32_t* bl = &blo[nt >> 1][(nt & 1) * 2];
                    mma16816(acc[mt][nt], ahi[mt], bh);
                    mma16816(acc[mt][nt], ahi[mt], bl);
                    mma16816(acc[mt][nt], alo[mt], bh);
                }
        }
        __syncthreads();
        if (kc + 2 < 1024 / BK)
            load_stage(sb, stg, kc + 2, Ahi, Alo, Bhi, Blo, m0, n0, tid);
        CP_COMMIT();
    }

    // epilogue
    const int erow = lane >> 2, ecol = (lane & 3) * 2;
#pragma unroll
    for (int mt = 0; mt < 4; mt++)
#pragma unroll
        for (int nt = 0; nt < 4; nt++) {
            size_t r0 = (size_t)(m0 + wm * 64 + mt * 16 + erow);
            int    c0 = n0 + wn * 32 + nt * 8 + ecol;
            *(float2*)(C + r0 * 1024 + c0)         = make_float2(acc[mt][nt][0], acc[mt][nt][1]);
            *(float2*)(C + (r0 + 8) * 1024 + c0)   = make_float2(acc[mt][nt][2], acc[mt][nt][3]);
        }
}

__global__ void __launch_bounds__(256, 1) tc_gemm_qkv() {
    const __nv_bfloat16 *bhi, *blo;
    float* C;
    if (blockIdx.z == 0)      { bhi = g_wqhi; blo = g_wqlo; C = g_q; }
    else if (blockIdx.z == 1) { bhi = g_wkhi; blo = g_wklo; C = g_k; }
    else                      { bhi = g_wvhi; blo = g_wvlo; C = g_v; }
    tc_gemm_body(g_xhi, g_xlo, bhi, blo, C);
}

__global__ void __launch_bounds__(256, 1) tc_gemm_out(float* __restrict__ out) {
    tc_gemm_body(g_yhi, g_ylo, g_wohi, g_wolo, out);
}

// ---------------------------------------------------------------------------
// RoPE (in-place on g_q / g_k)
// ---------------------------------------------------------------------------
__global__ void rope_kernel(const int* __restrict__ tok,
                            const int* __restrict__ use_rope,
                            const float* __restrict__ cs,
                            const float* __restrict__ sn) {
    if (use_rope[0] == 0) return;
    int idx = blockIdx.x * blockDim.x + threadIdx.x;
    int t   = idx >> 21;
    int rp  = idx & ((1 << 21) - 1);
    int row = rp >> 9;
    int pp  = rp & 511;
    int h   = pp >> 5, j = pp & 31;
    int s   = row & (S_ - 1);
    int pos = tok[s];
    float c  = cs[pos * 32 + j];
    float si = sn[pos * 32 + j];
    float* T = t ? g_k : g_q;
    float2* p = (float2*)(T + (size_t)row * D_ + h * HD_ + 2 * j);
    float2 v = *p;
    *p = make_float2(v.x * c - v.y * si, v.y * c + v.x * si);
}

// ---------------------------------------------------------------------------
// Flash attention, fp32, causal. Br=Bc=64, d=64. (unchanged)
// ---------------------------------------------------------------------------
__global__ void flash_kernel() {
    __shared__ __align__(16) float Qs [64][64];
    __shared__ __align__(16) float Kst[64][64];
    __shared__ __align__(16) float Vs [64][64];

    const int tid = threadIdx.x;
    const int tx = tid & 15, ty = tid >> 4;
    const int qt = blockIdx.x, h = blockIdx.y, b = blockIdx.z;
    const int q0 = qt * 64;
    const size_t baseQ = ((size_t)(b * S_) + q0) * D_ + h * HD_;

#pragma unroll
    for (int q = 0; q < 4; q++) {
        int l = q * 256 + tid;
        int r = l >> 4, c4 = (l & 15) * 4;
        *(float4*)&Qs[r][c4] = *(const float4*)(g_q + baseQ + (size_t)r * D_ + c4);
    }

    float m_i[4], l_i[4], o[4][4];
#pragma unroll
    for (int i = 0; i < 4; i++) {
        m_i[i] = -CUDART_INF_F; l_i[i] = 0.f;
#pragma unroll
        for (int j = 0; j < 4; j++) o[i][j] = 0.f;
    }

    for (int kt = 0; kt <= qt; kt++) {
        __syncthreads();
        const size_t baseK = ((size_t)(b * S_) + kt * 64) * D_ + h * HD_;
#pragma unroll
        for (int q = 0; q < 4; q++) {
            int l = q * 256 + tid;
            int r = l >> 4, c4 = (l & 15) * 4;
            float4 kv = *(const float4*)(g_k + baseK + (size_t)r * D_ + c4);
            Kst[c4+0][r] = kv.x; Kst[c4+1][r] = kv.y; Kst[c4+2][r] = kv.z; Kst[c4+3][r] = kv.w;
            *(float4*)&Vs[r][c4] = *(const float4*)(g_v + baseK + (size_t)r * D_ + c4);
        }
        __syncthreads();

        float s[4][4];
#pragma unroll
        for (int i = 0; i < 4; i++)
#pragma unroll
            for (int j = 0; j < 4; j++) s[i][j] = 0.f;

#pragma unroll 16
        for (int d = 0; d < 64; d++) {
            float kf[4];
            *(float4*)kf = *(const float4*)&Kst[d][tx*4];
#pragma unroll
            for (int i = 0; i < 4; i++) {
                float qv = Qs[ty*4 + i][d];
#pragma unroll
                for (int j = 0; j < 4; j++)
                    s[i][j] = fmaf(qv, kf[j], s[i][j]);
            }
        }

        const float scale = 0.125f;
        const int rowg = q0 + ty * 4, colg = kt * 64 + tx * 4;
        float mt[4];
#pragma unroll
        for (int i = 0; i < 4; i++) {
            mt[i] = -CUDART_INF_F;
#pragma unroll
            for (int j = 0; j < 4; j++) {
                float sv = s[i][j] * scale;
                if (colg + j > rowg + i) sv = -CUDART_INF_F;
                s[i][j] = sv;
                mt[i] = fmaxf(mt[i], sv);
            }
        }
#pragma unroll
        for (int off = 8; off > 0; off >>= 1)
#pragma unroll
            for (int i = 0; i < 4; i++)
                mt[i] = fmaxf(mt[i], __shfl_xor_sync(0xffffffffu, mt[i], off));

        float pt[4];
#pragma unroll
        for (int i = 0; i < 4; i++) {
            float mn = fmaxf(m_i[i], mt[i]);
            float alpha = __expf(m_i[i] - mn);
            m_i[i] = mn;
            pt[i] = 0.f;
#pragma unroll
            for (int j = 0; j < 4; j++) {
                s[i][j] = __expf(s[i][j] - mn);
                pt[i] += s[i][j];
            }
#pragma unroll
            for (int j = 0; j < 4; j++) o[i][j] *= alpha;
            l_i[i] *= alpha;
        }
#pragma unroll
        for (int off = 8; off > 0; off >>= 1)
#pragma unroll
            for (int i = 0; i < 4; i++)
                pt[i] += __shfl_xor_sync(0xffffffffu, pt[i], off);
#pragma unroll
        for (int i = 0; i < 4; i++) l_i[i] += pt[i];

        __syncthreads();
#pragma unroll
        for (int i = 0; i < 4; i++)
#pragma unroll
            for (int j = 0; j < 4; j++)
                Kst[ty*4 + i][tx*4 + j] = s[i][j];
        __syncthreads();

#pragma unroll 16
        for (int c = 0; c < 64; c++) {
            float vf[4];
            *(float4*)vf = *(const float4*)&Vs[c][tx*4];
#pragma unroll
            for (int i = 0; i < 4; i++) {
                float pv = Kst[ty*4 + i][c];
#pragma unroll
                for (int j = 0; j < 4; j++)
                    o[i][j] = fmaf(pv, vf[j], o[i][j]);
            }
        }
    }

#pragma unroll
    for (int i = 0; i < 4; i++) {
        float inv = 1.f / l_i[i];
        float4 ov = make_float4(o[i][0]*inv, o[i][1]*inv, o[i][2]*inv, o[i][3]*inv);
        *(float4*)(g_y + baseQ + (size_t)(ty*4 + i) * D_ + tx*4) = ov;
    }
}

// ---------------------------------------------------------------------------
extern "C" void kernel_launch(void* const* d_in, const int* in_sizes, int n_in,
                              void* d_out, int out_size) {
    const float* x        = (const float*)d_in[0];
    const int*   tok      = (const int*)  d_in[1];
    const int*   use_rope = (const int*)  d_in[2];
    const float* Wq       = (const float*)d_in[3];
    const float* Wk       = (const float*)d_in[4];
    const float* Wv       = (const float*)d_in[5];
    const float* Wo       = (const float*)d_in[6];
    const float* cs       = (const float*)d_in[7];
    const float* sn       = (const float*)d_in[8];
    float* out = (float*)d_out;

    void *p_xhi, *p_xlo, *p_yhi, *p_ylo, *p_y;
    void *p_wqhi, *p_wqlo, *p_wkhi, *p_wklo, *p_wvhi, *p_wvlo, *p_wohi, *p_wolo;
    cudaGetSymbolAddress(&p_xhi, g_xhi);   cudaGetSymbolAddress(&p_xlo, g_xlo);
    cudaGetSymbolAddress(&p_yhi, g_yhi);   cudaGetSymbolAddress(&p_ylo, g_ylo);
    cudaGetSymbolAddress(&p_y,   g_y);
    cudaGetSymbolAddress(&p_wqhi, g_wqhi); cudaGetSymbolAddress(&p_wqlo, g_wqlo);
    cudaGetSymbolAddress(&p_wkhi, g_wkhi); cudaGetSymbolAddress(&p_wklo, g_wklo);
    cudaGetSymbolAddress(&p_wvhi, g_wvhi); cudaGetSymbolAddress(&p_wvlo, g_wvlo);
    cudaGetSymbolAddress(&p_wohi, g_wohi); cudaGetSymbolAddress(&p_wolo, g_wolo);

    cudaFuncSetAttribute(tc_gemm_qkv, cudaFuncAttributeMaxDynamicSharedMemorySize, GEMM_SMEM);
    cudaFuncSetAttribute(tc_gemm_out, cudaFuncAttributeMaxDynamicSharedMemorySize, GEMM_SMEM);

    const int nx4 = (B_*S_*D_) / 4;
    const int nw4 = (D_*D_) / 4;

    split_kernel<<<(nx4 + 255) / 256, 256>>>(x,  (__nv_bfloat16*)p_xhi, (__nv_bfloat16*)p_xlo, nx4);
    split_kernel<<<(nw4 + 255) / 256, 256>>>(Wq, (__nv_bfloat16*)p_wqhi, (__nv_bfloat16*)p_wqlo, nw4);
    split_kernel<<<(nw4 + 255) / 256, 256>>>(Wk, (__nv_bfloat16*)p_wkhi, (__nv_bfloat16*)p_wklo, nw4);
    split_kernel<<<(nw4 + 255) / 256, 256>>>(Wv, (__nv_bfloat16*)p_wvhi, (__nv_bfloat16*)p_wvlo, nw4);
    split_kernel<<<(nw4 + 255) / 256, 256>>>(Wo, (__nv_bfloat16*)p_wohi, (__nv_bfloat16*)p_wolo, nw4);

    tc_gemm_qkv<<<dim3(8, 32, 3), 256, GEMM_SMEM>>>();
    rope_kernel<<<(2u * B_ * S_ * (D_ / 2)) / 256u, 256>>>(tok, use_rope, cs, sn);
    flash_kernel<<<dim3(S_ / 64, H_, B_), 256>>>();

    split_kernel<<<(nx4 + 255) / 256, 256>>>((const float*)p_y, (__nv_bfloat16*)p_yhi, (__nv_bfloat16*)p_ylo, nx4);
    tc_gemm_out<<<dim3(8, 32), 256, GEMM_SMEM>>>(out);
}

// round 4
// speedup vs baseline: 2.4980x; 1.7781x over previous
#include <cuda_runtime.h>
#include <cuda_bf16.h>
#include <math_constants.h>
#include <cstdint>

#define B_  2
#define S_  2048
#define D_  1024
#define H_  16
#define HD_ 64

// ---------------------------------------------------------------------------
// Scratch (__device__ globals; allocation-free rule)
// ---------------------------------------------------------------------------
__device__ float g_q[B_*S_*D_];
__device__ float g_k[B_*S_*D_];
__device__ float g_v[B_*S_*D_];
__device__ float g_y[B_*S_*D_];

__device__ __align__(16) __nv_bfloat16 g_xhi[B_*S_*D_], g_xlo[B_*S_*D_];
__device__ __align__(16) __nv_bfloat16 g_yhi[B_*S_*D_], g_ylo[B_*S_*D_];
__device__ __align__(16) __nv_bfloat16 g_qhi[B_*S_*D_], g_qlo[B_*S_*D_];
__device__ __align__(16) __nv_bfloat16 g_khi[B_*S_*D_], g_klo[B_*S_*D_];
__device__ __align__(16) __nv_bfloat16 g_vhi[B_*S_*D_], g_vlo[B_*S_*D_];
__device__ __align__(16) __nv_bfloat16 g_wqhi[D_*D_], g_wqlo[D_*D_];
__device__ __align__(16) __nv_bfloat16 g_wkhi[D_*D_], g_wklo[D_*D_];
__device__ __align__(16) __nv_bfloat16 g_wvhi[D_*D_], g_wvlo[D_*D_];
__device__ __align__(16) __nv_bfloat16 g_wohi[D_*D_], g_wolo[D_*D_];

// ---------------------------------------------------------------------------
// Low-level helpers (base-target instructions only)
// ---------------------------------------------------------------------------
__device__ __forceinline__ uint32_t smem_to_u32(const void* p) {
    uint32_t a;
    asm("{ .reg .u64 t; cvta.to.shared.u64 t, %1; cvt.u32.u64 %0, t; }" : "=r"(a) : "l"(p));
    return a;
}

__device__ __forceinline__ void cp16(uint32_t saddr, const void* gaddr) {
    asm volatile("cp.async.cg.shared.global [%0], [%1], 16;" :: "r"(saddr), "l"(gaddr));
}
#define CP_COMMIT() asm volatile("cp.async.commit_group;" ::: "memory")
#define CP_WAIT1()  asm volatile("cp.async.wait_group 1;"  ::: "memory")

__device__ __forceinline__ void ldmx4(uint32_t* r, uint32_t addr) {
    asm volatile("ldmatrix.sync.aligned.m8n8.x4.shared.b16 {%0,%1,%2,%3}, [%4];"
        : "=r"(r[0]), "=r"(r[1]), "=r"(r[2]), "=r"(r[3]) : "r"(addr));
}
__device__ __forceinline__ void ldmx4t(uint32_t* r, uint32_t addr) {
    asm volatile("ldmatrix.sync.aligned.m8n8.x4.trans.shared.b16 {%0,%1,%2,%3}, [%4];"
        : "=r"(r[0]), "=r"(r[1]), "=r"(r[2]), "=r"(r[3]) : "r"(addr));
}

__device__ __forceinline__ void mma16816(float* c, const uint32_t* a, const uint32_t* b) {
    asm volatile(
        "mma.sync.aligned.m16n8k16.row.col.f32.bf16.bf16.f32 "
        "{%0,%1,%2,%3}, {%4,%5,%6,%7}, {%8,%9}, {%0,%1,%2,%3};"
        : "+f"(c[0]), "+f"(c[1]), "+f"(c[2]), "+f"(c[3])
        : "r"(a[0]), "r"(a[1]), "r"(a[2]), "r"(a[3]), "r"(b[0]), "r"(b[1]));
}

__device__ __forceinline__ uint16_t bf16u(float f) {
    return __bfloat16_as_ushort(__float2bfloat16(f));
}
__device__ __forceinline__ float bf16f(float f) {
    return __bfloat162float(__float2bfloat16(f));
}

// ---------------------------------------------------------------------------
// Split fp32 -> (hi, lo) bf16
// ---------------------------------------------------------------------------
__global__ void split_kernel(const float* __restrict__ src,
                             __nv_bfloat16* __restrict__ hi,
                             __nv_bfloat16* __restrict__ lo, int n4) {
    int i = blockIdx.x * blockDim.x + threadIdx.x;
    if (i >= n4) return;
    float4 v = ((const float4*)src)[i];
    float vv[4] = {v.x, v.y, v.z, v.w};
    unsigned short hs[4], ls[4];
#pragma unroll
    for (int j = 0; j < 4; j++) {
        float hf = bf16f(vv[j]);
        hs[j] = bf16u(vv[j]);
        ls[j] = bf16u(vv[j] - hf);
    }
    ((ushort4*)hi)[i] = make_ushort4(hs[0], hs[1], hs[2], hs[3]);
    ((ushort4*)lo)[i] = make_ushort4(ls[0], ls[1], ls[2], ls[3]);
}

// ---------------------------------------------------------------------------
// mma.sync bf16 split GEMM (unchanged from R3): C = A @ B^T, K=N=1024.
// ---------------------------------------------------------------------------
#define BK     32
#define PAD    40
#define TILE_B (128 * PAD * 2)
#define STAGE_B (4 * TILE_B)
#define GEMM_SMEM (2 * STAGE_B)

__device__ __forceinline__ void load_stage(uint32_t sb, int stg, int kc,
        const __nv_bfloat16* __restrict__ Ahi, const __nv_bfloat16* __restrict__ Alo,
        const __nv_bfloat16* __restrict__ Bhi, const __nv_bfloat16* __restrict__ Blo,
        int m0, int n0, int tid) {
    const __nv_bfloat16* srcs[4] = {Ahi, Alo, Bhi, Blo};
    const int r0s[4] = {m0, m0, n0, n0};
    uint32_t base = sb + stg * STAGE_B;
#pragma unroll
    for (int t = 0; t < 4; t++) {
        const __nv_bfloat16* src = srcs[t];
        const int r0 = r0s[t];
        uint32_t tb = base + t * TILE_B;
#pragma unroll
        for (int it = 0; it < 2; it++) {
            int seg = it * 256 + tid;
            int r = seg >> 2, c8 = (seg & 3) * 8;
            cp16(tb + (r * PAD + c8) * 2,
                 src + (size_t)(r0 + r) * 1024 + kc * BK + c8);
        }
    }
}

__device__ __forceinline__ void tc_gemm_body(
        const __nv_bfloat16* __restrict__ Ahi, const __nv_bfloat16* __restrict__ Alo,
        const __nv_bfloat16* __restrict__ Bhi, const __nv_bfloat16* __restrict__ Blo,
        float* __restrict__ C) {
    extern __shared__ char smem[];
    const uint32_t sb = smem_to_u32(smem);
    const int tid = threadIdx.x, lane = tid & 31, warp = tid >> 5;
    const int wm = warp >> 2, wn = warp & 3;
    const int m0 = blockIdx.y * 128, n0 = blockIdx.x * 128;

    float acc[4][4][4];
#pragma unroll
    for (int i = 0; i < 4; i++)
#pragma unroll
        for (int j = 0; j < 4; j++)
#pragma unroll
            for (int e = 0; e < 4; e++) acc[i][j][e] = 0.f;

    load_stage(sb, 0, 0, Ahi, Alo, Bhi, Blo, m0, n0, tid);
    CP_COMMIT();
    load_stage(sb, 1, 1, Ahi, Alo, Bhi, Blo, m0, n0, tid);
    CP_COMMIT();

    const int a_row = lane & 15;
    const int a_coff = (lane >> 4) * 8;
    const int b_row = (lane & 7) + ((lane >> 4) << 3);
    const int b_coff = ((lane >> 3) & 1) * 8;

    for (int kc = 0; kc < 1024 / BK; kc++) {
        CP_WAIT1();
        __syncthreads();
        const int stg = kc & 1;
        const uint32_t aHiB = sb + stg * STAGE_B;
        const uint32_t aLoB = aHiB + TILE_B;
        const uint32_t bHiB = aLoB + TILE_B;
        const uint32_t bLoB = bHiB + TILE_B;

#pragma unroll
        for (int ks = 0; ks < 2; ks++) {
            const int k0 = ks * 16;
            uint32_t ahi[4][4], alo[4][4];
#pragma unroll
            for (int mt = 0; mt < 4; mt++) {
                uint32_t off = (uint32_t)(((wm * 64 + mt * 16 + a_row) * PAD + k0 + a_coff) * 2);
                ldmx4(ahi[mt], aHiB + off);
                ldmx4(alo[mt], aLoB + off);
            }
            uint32_t bhi[2][4], blo[2][4];
#pragma unroll
            for (int nt2 = 0; nt2 < 2; nt2++) {
                uint32_t off = (uint32_t)(((wn * 32 + nt2 * 16 + b_row) * PAD + k0 + b_coff) * 2);
                ldmx4(bhi[nt2], bHiB + off);
                ldmx4(blo[nt2], bLoB + off);
            }
#pragma unroll
            for (int mt = 0; mt < 4; mt++)
#pragma unroll
                for (int nt = 0; nt < 4; nt++) {
                    const uint32_t* bh = &bhi[nt >> 1][(nt & 1) * 2];
                    const uint32_t* bl = &blo[nt >> 1][(nt & 1) * 2];
                    mma16816(acc[mt][nt], ahi[mt], bh);
                    mma16816(acc[mt][nt], ahi[mt], bl);
                    mma16816(acc[mt][nt], alo[mt], bh);
                }
        }
        __syncthreads();
        if (kc + 2 < 1024 / BK)
            load_stage(sb, stg, kc + 2, Ahi, Alo, Bhi, Blo, m0, n0, tid);
        CP_COMMIT();
    }

    const int erow = lane >> 2, ecol = (lane & 3) * 2;
#pragma unroll
    for (int mt = 0; mt < 4; mt++)
#pragma unroll
        for (int nt = 0; nt < 4; nt++) {
            size_t r0 = (size_t)(m0 + wm * 64 + mt * 16 + erow);
            int    c0 = n0 + wn * 32 + nt * 8 + ecol;
            *(float2*)(C + r0 * 1024 + c0)       = make_float2(acc[mt][nt][0], acc[mt][nt][1]);
            *(float2*)(C + (r0 + 8) * 1024 + c0) = make_float2(acc[mt][nt][2], acc[mt][nt][3]);
        }
}

__global__ void __launch_bounds__(256, 1) tc_gemm_qkv() {
    const __nv_bfloat16 *bhi, *blo;
    float* C;
    if (blockIdx.z == 0)      { bhi = g_wqhi; blo = g_wqlo; C = g_q; }
    else if (blockIdx.z == 1) { bhi = g_wkhi; blo = g_wklo; C = g_k; }
    else                      { bhi = g_wvhi; blo = g_wvlo; C = g_v; }
    tc_gemm_body(g_xhi, g_xlo, bhi, blo, C);
}

__global__ void __launch_bounds__(256, 1) tc_gemm_out(float* __restrict__ out) {
    tc_gemm_body(g_yhi, g_ylo, g_wohi, g_wolo, out);
}

// ---------------------------------------------------------------------------
// RoPE + split: read fp32 q/k, rotate (if use_rope), write hi/lo bf16.
// ---------------------------------------------------------------------------
__global__ void rope_split_kernel(const int* __restrict__ tok,
                                  const int* __restrict__ use_rope,
                                  const float* __restrict__ cs,
                                  const float* __restrict__ sn) {
    int idx = blockIdx.x * blockDim.x + threadIdx.x;   // 0 .. 2*4096*512-1
    int t   = idx >> 21;
    int rp  = idx & ((1 << 21) - 1);
    int row = rp >> 9;
    int pp  = rp & 511;
    int h   = pp >> 5, j = pp & 31;
    int s   = row & (S_ - 1);
    float c = 1.f, si = 0.f;
    if (use_rope[0]) {
        int pos = tok[s];
        c  = cs[pos * 32 + j];
        si = sn[pos * 32 + j];
    }
    const float* T = t ? g_k : g_q;
    size_t off = (size_t)row * D_ + h * HD_ + 2 * j;
    float2 v = *(const float2*)(T + off);
    float rx = v.x * c - v.y * si;
    float ry = v.y * c + v.x * si;
    __nv_bfloat16* Hi = t ? g_khi : g_qhi;
    __nv_bfloat16* Lo = t ? g_klo : g_qlo;
    ushort2 hs = make_ushort2(bf16u(rx), bf16u(ry));
    ushort2 ls = make_ushort2(bf16u(rx - bf16f(rx)), bf16u(ry - bf16f(ry)));
    *(ushort2*)(Hi + off) = hs;
    *(ushort2*)(Lo + off) = ls;
}

// ---------------------------------------------------------------------------
// Flash attention with mma.sync split-bf16. Br=128, Bc=64, d=64.
// 256 threads = 8 warps; warp w owns rows 16w..16w+15 of the Q tile.
// ---------------------------------------------------------------------------
#define FPAD   72
#define QT_B   (128 * FPAD * 2)            // 18432 B per Q tile (hi or lo)
#define KV_OFF (2 * QT_B)                  // 36864
#define KVT_B  (64 * FPAD * 2)             // 9216 B per K/V tile
#define FSTG_B (4 * KVT_B)                 // 36864 per stage (khi,klo,vhi,vlo)
#define FLASH_SMEM (KV_OFF + 2 * FSTG_B)   // 110592 B

__device__ __forceinline__ void flash_load_kv(uint32_t sb, int stg, int kt,
                                              int b, int h, int tid) {
    uint32_t base = sb + KV_OFF + stg * FSTG_B;
    size_t krow0 = (size_t)(b * S_ + kt * 64);
    const __nv_bfloat16* srcs[4] = {g_khi, g_klo, g_vhi, g_vlo};
#pragma unroll
    for (int t = 0; t < 4; t++) {
#pragma unroll
        for (int it = 0; it < 2; it++) {
            int seg = it * 256 + tid;
            int r = seg >> 3, c8 = (seg & 7) * 8;
            cp16(base + t * KVT_B + (r * FPAD + c8) * 2,
                 srcs[t] + (krow0 + r) * 1024 + h * HD_ + c8);
        }
    }
}

__global__ void __launch_bounds__(256, 1) flash_mma_kernel() {
    extern __shared__ char fsm[];
    const uint32_t sb = smem_to_u32(fsm);
    const int tid = threadIdx.x, lane = tid & 31, warp = tid >> 5;
    const int qt = blockIdx.x, h = blockIdx.y, b = blockIdx.z;
    const int q0 = qt * 128;
    const size_t qrow0 = (size_t)(b * S_ + q0);
    const int nb = 2 * (qt + 1);

    // async-load Q tiles (hi, lo)
    {
        const __nv_bfloat16* qs[2] = {g_qhi, g_qlo};
#pragma unroll
        for (int t = 0; t < 2; t++)
#pragma unroll
            for (int it = 0; it < 4; it++) {
                int seg = it * 256 + tid;
                int r = seg >> 3, c8 = (seg & 7) * 8;
                cp16(sb + t * QT_B + (r * FPAD + c8) * 2,
                     qs[t] + (qrow0 + r) * 1024 + h * HD_ + c8);
            }
    }
    CP_COMMIT();
    flash_load_kv(sb, 0, 0, b, h, tid);
    CP_COMMIT();
    flash_load_kv(sb, 1, 1, b, h, tid);
    CP_COMMIT();

    float oacc[8][4];
#pragma unroll
    for (int nt = 0; nt < 8; nt++)
#pragma unroll
        for (int e = 0; e < 4; e++) oacc[nt][e] = 0.f;
    float m_i[2] = {-1e30f, -1e30f}, l_i[2] = {0.f, 0.f};

    const int a_row = lane & 15;
    const int a_coff = (lane >> 4) * 8;
    const int b_row = (lane & 7) + ((lane >> 4) << 3);
    const int b_coff = ((lane >> 3) & 1) * 8;
    const int wm16 = warp * 16;
    const int vt = lane >> 3, vi = lane & 7;     // V trans-ldmatrix tile/row

    for (int kt = 0; kt < nb; kt++) {
        CP_WAIT1();
        __syncthreads();
        const uint32_t kb = sb + KV_OFF + (kt & 1) * FSTG_B;

        // ---- S = Q @ K^T (3-pass split) ----
        float sacc[8][4];
#pragma unroll
        for (int nt = 0; nt < 8; nt++)
#pragma unroll
            for (int e = 0; e < 4; e++) sacc[nt][e] = 0.f;

#pragma unroll
        for (int ks = 0; ks < 4; ks++) {
            const int k0 = ks * 16;
            uint32_t aqh[4], aql[4];
            uint32_t qoff = (uint32_t)(((wm16 + a_row) * FPAD + k0 + a_coff) * 2);
            ldmx4(aqh, sb + qoff);
            ldmx4(aql, sb + QT_B + qoff);
            uint32_t bkh[4][4], bkl[4][4];
#pragma unroll
            for (int nt2 = 0; nt2 < 4; nt2++) {
                uint32_t off = (uint32_t)(((nt2 * 16 + b_row) * FPAD + k0 + b_coff) * 2);
                ldmx4(bkh[nt2], kb + off);
                ldmx4(bkl[nt2], kb + KVT_B + off);
            }
#pragma unroll
            for (int nt = 0; nt < 8; nt++) {
                const uint32_t* bh = &bkh[nt >> 1][(nt & 1) * 2];
                const uint32_t* bl = &bkl[nt >> 1][(nt & 1) * 2];
                mma16816(sacc[nt], aqh, bh);
                mma16816(sacc[nt], aqh, bl);
                mma16816(sacc[nt], aql, bh);
            }
        }

        // ---- scale + causal mask + row max ----
        const int rbase = q0 + wm16 + (lane >> 2);
        const int cbase = kt * 64 + 2 * (lane & 3);
        float mt[2] = {-1e30f, -1e30f};
#pragma unroll
        for (int nt = 0; nt < 8; nt++)
#pragma unroll
            for (int e = 0; e < 4; e++) {
                int col = cbase + nt * 8 + (e & 1);
                int row = rbase + ((e >> 1) << 3);
                float sv = sacc[nt][e] * 0.125f;
                if (col > row) sv = -1e30f;
                sacc[nt][e] = sv;
                mt[e >> 1] = fmaxf(mt[e >> 1], sv);
            }
#pragma unroll
        for (int off = 1; off <= 2; off <<= 1)
#pragma unroll
            for (int rh = 0; rh < 2; rh++)
                mt[rh] = fmaxf(mt[rh], __shfl_xor_sync(0xffffffffu, mt[rh], off));

        float mn[2], alpha[2];
#pragma unroll
        for (int rh = 0; rh < 2; rh++) {
            mn[rh] = fmaxf(m_i[rh], mt[rh]);
            alpha[rh] = __expf(m_i[rh] - mn[rh]);
            m_i[rh] = mn[rh];
        }

        // ---- exp + split P to bf16 hi/lo packed frags ----
        uint32_t phi[8][2], plo[8][2];
        float psum[2] = {0.f, 0.f};
#pragma unroll
        for (int nt = 0; nt < 8; nt++) {
#pragma unroll
            for (int hf = 0; hf < 2; hf++) {
                float p0 = __expf(sacc[nt][hf * 2]     - mn[hf]);
                float p1 = __expf(sacc[nt][hf * 2 + 1] - mn[hf]);
                psum[hf] += p0 + p1;
                uint16_t h0 = bf16u(p0), h1 = bf16u(p1);
                phi[nt][hf] = (uint32_t)h0 | ((uint32_t)h1 << 16);
                uint16_t l0 = bf16u(p0 - bf16f(p0)), l1 = bf16u(p1 - bf16f(p1));
                plo[nt][hf] = (uint32_t)l0 | ((uint32_t)l1 << 16);
            }
        }
#pragma unroll
        for (int off = 1; off <= 2; off <<= 1)
#pragma unroll
            for (int rh = 0; rh < 2; rh++)
                psum[rh] += __shfl_xor_sync(0xffffffffu, psum[rh], off);
#pragma unroll
        for (int rh = 0; rh < 2; rh++)
            l_i[rh] = l_i[rh] * alpha[rh] + psum[rh];

        // rescale O
#pragma unroll
        for (int nt = 0; nt < 8; nt++) {
            oacc[nt][0] *= alpha[0]; oacc[nt][1] *= alpha[0];
            oacc[nt][2] *= alpha[1]; oacc[nt][3] *= alpha[1];
        }

        // ---- O += P @ V (3-pass split), V via ldmatrix.trans ----
#pragma unroll
        for (int ks = 0; ks < 4; ks++) {
            uint32_t pah[4] = {phi[2*ks][0], phi[2*ks][1], phi[2*ks+1][0], phi[2*ks+1][1]};
            uint32_t pal[4] = {plo[2*ks][0], plo[2*ks][1], plo[2*ks+1][0], plo[2*ks+1][1]};
#pragma unroll
            for (int ntp = 0; ntp < 4; ntp++) {
                uint32_t vaddr = kb + 2 * KVT_B +
                    (uint32_t)(((ks * 16 + (vt & 1) * 8 + vi) * FPAD + ntp * 16 + (vt >> 1) * 8) * 2);
                uint32_t vh[4], vl[4];
                ldmx4t(vh, vaddr);
                ldmx4t(vl, vaddr + KVT_B);
                mma16816(oacc[2*ntp],   pah, &vh[0]);
                mma16816(oacc[2*ntp],   pah, &vl[0]);
                mma16816(oacc[2*ntp],   pal, &vh[0]);
                mma16816(oacc[2*ntp+1], pah, &vh[2]);
                mma16816(oacc[2*ntp+1], pah, &vl[2]);
                mma16816(oacc[2*ntp+1], pal, &vh[2]);
            }
        }

        __syncthreads();
        if (kt + 2 < nb)
            flash_load_kv(sb, kt & 1, kt + 2, b, h, tid);
        CP_COMMIT();
    }

    // ---- epilogue ----
    float inv0 = 1.f / l_i[0], inv1 = 1.f / l_i[1];
    size_t row0 = qrow0 + wm16 + (lane >> 2);
    int colb = h * HD_ + 2 * (lane & 3);
#pragma unroll
    for (int nt = 0; nt < 8; nt++) {
        int col = colb + nt * 8;
        *(float2*)(g_y + row0 * 1024 + col)       = make_float2(oacc[nt][0] * inv0, oacc[nt][1] * inv0);
        *(float2*)(g_y + (row0 + 8) * 1024 + col) = make_float2(oacc[nt][2] * inv1, oacc[nt][3] * inv1);
    }
}

// ---------------------------------------------------------------------------
extern "C" void kernel_launch(void* const* d_in, const int* in_sizes, int n_in,
                              void* d_out, int out_size) {
    const float* x        = (const float*)d_in[0];
    const int*   tok      = (const int*)  d_in[1];
    const int*   use_rope = (const int*)  d_in[2];
    const float* Wq       = (const float*)d_in[3];
    const float* Wk       = (const float*)d_in[4];
    const float* Wv       = (const float*)d_in[5];
    const float* Wo       = (const float*)d_in[6];
    const float* cs       = (const float*)d_in[7];
    const float* sn       = (const float*)d_in[8];
    float* out = (float*)d_out;

    void *p_xhi, *p_xlo, *p_yhi, *p_ylo, *p_y, *p_v, *p_vhi, *p_vlo;
    void *p_wqhi, *p_wqlo, *p_wkhi, *p_wklo, *p_wvhi, *p_wvlo, *p_wohi, *p_wolo;
    cudaGetSymbolAddress(&p_xhi, g_xhi);   cudaGetSymbolAddress(&p_xlo, g_xlo);
    cudaGetSymbolAddress(&p_yhi, g_yhi);   cudaGetSymbolAddress(&p_ylo, g_ylo);
    cudaGetSymbolAddress(&p_y,   g_y);
    cudaGetSymbolAddress(&p_v,   g_v);
    cudaGetSymbolAddress(&p_vhi, g_vhi);   cudaGetSymbolAddress(&p_vlo, g_vlo);
    cudaGetSymbolAddress(&p_wqhi, g_wqhi); cudaGetSymbolAddress(&p_wqlo, g_wqlo);
    cudaGetSymbolAddress(&p_wkhi, g_wkhi); cudaGetSymbolAddress(&p_wklo, g_wklo);
    cudaGetSymbolAddress(&p_wvhi, g_wvhi); cudaGetSymbolAddress(&p_wvlo, g_wvlo);
    cudaGetSymbolAddress(&p_wohi, g_wohi); cudaGetSymbolAddress(&p_wolo, g_wolo);

    cudaFuncSetAttribute(tc_gemm_qkv, cudaFuncAttributeMaxDynamicSharedMemorySize, GEMM_SMEM);
    cudaFuncSetAttribute(tc_gemm_out, cudaFuncAttributeMaxDynamicSharedMemorySize, GEMM_SMEM);
    cudaFuncSetAttribute(flash_mma_kernel, cudaFuncAttributeMaxDynamicSharedMemorySize, FLASH_SMEM);

    const int nx4 = (B_*S_*D_) / 4;
    const int nw4 = (D_*D_) / 4;

    split_kernel<<<(nx4 + 255) / 256, 256>>>(x,  (__nv_bfloat16*)p_xhi, (__nv_bfloat16*)p_xlo, nx4);
    split_kernel<<<(nw4 + 255) / 256, 256>>>(Wq, (__nv_bfloat16*)p_wqhi, (__nv_bfloat16*)p_wqlo, nw4);
    split_kernel<<<(nw4 + 255) / 256, 256>>>(Wk, (__nv_bfloat16*)p_wkhi, (__nv_bfloat16*)p_wklo, nw4);
    split_kernel<<<(nw4 + 255) / 256, 256>>>(Wv, (__nv_bfloat16*)p_wvhi, (__nv_bfloat16*)p_wvlo, nw4);
    split_kernel<<<(nw4 + 255) / 256, 256>>>(Wo, (__nv_bfloat16*)p_wohi, (__nv_bfloat16*)p_wolo, nw4);

    tc_gemm_qkv<<<dim3(8, 32, 3), 256, GEMM_SMEM>>>();

    rope_split_kernel<<<(2u * B_ * S_ * (D_ / 2)) / 256u, 256>>>(tok, use_rope, cs, sn);
    split_kernel<<<(nx4 + 255) / 256, 256>>>((const float*)p_v, (__nv_bfloat16*)p_vhi, (__nv_bfloat16*)p_vlo, nx4);

    flash_mma_kernel<<<dim3(S_ / 128, H_, B_), 256, FLASH_SMEM>>>();

    split_kernel<<<(nx4 + 255) / 256, 256>>>((const float*)p_y, (__nv_bfloat16*)p_yhi, (__nv_bfloat16*)p_ylo, nx4);
    tc_gemm_out<<<dim3(8, 32), 256, GEMM_SMEM>>>(out);
}

// round 5
// speedup vs baseline: 3.7650x; 1.5072x over previous
#include <cuda_runtime.h>
#include <cuda_fp16.h>
#include <math_constants.h>
#include <cstdint>

#define B_  2
#define S_  2048
#define D_  1024
#define H_  16
#define HD_ 64

// ---------------------------------------------------------------------------
// Scratch (__device__ globals; allocation-free rule)
// ---------------------------------------------------------------------------
__device__ float g_q[B_*S_*D_];
__device__ float g_k[B_*S_*D_];
__device__ float g_v[B_*S_*D_];

__device__ __align__(16) __half g_xhi[B_*S_*D_], g_xlo[B_*S_*D_];
__device__ __align__(16) __half g_yhi[B_*S_*D_], g_ylo[B_*S_*D_];
__device__ __align__(16) __half g_qhi[B_*S_*D_], g_qlo[B_*S_*D_];
__device__ __align__(16) __half g_khi[B_*S_*D_];
__device__ __align__(16) __half g_vhi[B_*S_*D_];
__device__ __align__(16) __half g_wqhi[D_*D_];
__device__ __align__(16) __half g_wkhi[D_*D_];
__device__ __align__(16) __half g_wvhi[D_*D_];
__device__ __align__(16) __half g_wohi[D_*D_];

// ---------------------------------------------------------------------------
// Low-level helpers (base-target instructions only)
// ---------------------------------------------------------------------------
__device__ __forceinline__ uint32_t smem_to_u32(const void* p) {
    uint32_t a;
    asm("{ .reg .u64 t; cvta.to.shared.u64 t, %1; cvt.u32.u64 %0, t; }" : "=r"(a) : "l"(p));
    return a;
}

__device__ __forceinline__ void cp16(uint32_t saddr, const void* gaddr) {
    asm volatile("cp.async.cg.shared.global [%0], [%1], 16;" :: "r"(saddr), "l"(gaddr));
}
#define CP_COMMIT() asm volatile("cp.async.commit_group;" ::: "memory")
#define CP_WAIT1()  asm volatile("cp.async.wait_group 1;"  ::: "memory")

__device__ __forceinline__ void ldmx4(uint32_t* r, uint32_t addr) {
    asm volatile("ldmatrix.sync.aligned.m8n8.x4.shared.b16 {%0,%1,%2,%3}, [%4];"
        : "=r"(r[0]), "=r"(r[1]), "=r"(r[2]), "=r"(r[3]) : "r"(addr));
}
__device__ __forceinline__ void ldmx4t(uint32_t* r, uint32_t addr) {
    asm volatile("ldmatrix.sync.aligned.m8n8.x4.trans.shared.b16 {%0,%1,%2,%3}, [%4];"
        : "=r"(r[0]), "=r"(r[1]), "=r"(r[2]), "=r"(r[3]) : "r"(addr));
}

__device__ __forceinline__ void mma16816(float* c, const uint32_t* a, const uint32_t* b) {
    asm volatile(
        "mma.sync.aligned.m16n8k16.row.col.f32.f16.f16.f32 "
        "{%0,%1,%2,%3}, {%4,%5,%6,%7}, {%8,%9}, {%0,%1,%2,%3};"
        : "+f"(c[0]), "+f"(c[1]), "+f"(c[2]), "+f"(c[3])
        : "r"(a[0]), "r"(a[1]), "r"(a[2]), "r"(a[3]), "r"(b[0]), "r"(b[1]));
}

__device__ __forceinline__ uint16_t h16u(float f) { return __half_as_ushort(__float2half(f)); }
__device__ __forceinline__ float    h16f(float f) { return __half2float(__float2half(f)); }

// ---------------------------------------------------------------------------
// Splits: fp32 -> (hi, lo) fp16, and fp32 -> hi fp16 only
// ---------------------------------------------------------------------------
__global__ void split2_kernel(const float* __restrict__ src,
                              __half* __restrict__ hi,
                              __half* __restrict__ lo, int n4) {
    int i = blockIdx.x * blockDim.x + threadIdx.x;
    if (i >= n4) return;
    float4 v = ((const float4*)src)[i];
    float vv[4] = {v.x, v.y, v.z, v.w};
    unsigned short hs[4], ls[4];
#pragma unroll
    for (int j = 0; j < 4; j++) {
        float hf = h16f(vv[j]);
        hs[j] = h16u(vv[j]);
        ls[j] = h16u(vv[j] - hf);
    }
    ((ushort4*)hi)[i] = make_ushort4(hs[0], hs[1], hs[2], hs[3]);
    ((ushort4*)lo)[i] = make_ushort4(ls[0], ls[1], ls[2], ls[3]);
}

__global__ void split1_kernel(const float* __restrict__ src,
                              __half* __restrict__ hi, int n4) {
    int i = blockIdx.x * blockDim.x + threadIdx.x;
    if (i >= n4) return;
    float4 v = ((const float4*)src)[i];
    ((ushort4*)hi)[i] = make_ushort4(h16u(v.x), h16u(v.y), h16u(v.z), h16u(v.w));
}

// ---------------------------------------------------------------------------
// mma.sync fp16 2-pass GEMM: C = A @ B^T, K=N=1024; A corrected (hi+lo), B hi.
// 128x128 CTA tile, BK=32, 256 threads (8 warps 2x4), warp tile 64x32.
// ---------------------------------------------------------------------------
#define BK     32
#define PAD    40
#define TILE_B (128 * PAD * 2)          // 10240 B
#define STAGE_B (3 * TILE_B)            // Ahi, Alo, Bhi = 30720 B
#define GEMM_SMEM (2 * STAGE_B)         // 61440 B

__device__ __forceinline__ void load_stage(uint32_t sb, int stg, int kc,
        const __half* __restrict__ Ahi, const __half* __restrict__ Alo,
        const __half* __restrict__ Bhi,
        int m0, int n0, int tid) {
    const __half* srcs[3] = {Ahi, Alo, Bhi};
    const int r0s[3] = {m0, m0, n0};
    uint32_t base = sb + stg * STAGE_B;
#pragma unroll
    for (int t = 0; t < 3; t++) {
        const __half* src = srcs[t];
        const int r0 = r0s[t];
        uint32_t tb = base + t * TILE_B;
#pragma unroll
        for (int it = 0; it < 2; it++) {
            int seg = it * 256 + tid;
            int r = seg >> 2, c8 = (seg & 3) * 8;
            cp16(tb + (r * PAD + c8) * 2,
                 src + (size_t)(r0 + r) * 1024 + kc * BK + c8);
        }
    }
}

__device__ __forceinline__ void tc_gemm_body(
        const __half* __restrict__ Ahi, const __half* __restrict__ Alo,
        const __half* __restrict__ Bhi,
        float* __restrict__ C) {
    extern __shared__ char smem[];
    const uint32_t sb = smem_to_u32(smem);
    const int tid = threadIdx.x, lane = tid & 31, warp = tid >> 5;
    const int wm = warp >> 2, wn = warp & 3;
    const int m0 = blockIdx.y * 128, n0 = blockIdx.x * 128;

    float acc[4][4][4];
#pragma unroll
    for (int i = 0; i < 4; i++)
#pragma unroll
        for (int j = 0; j < 4; j++)
#pragma unroll
            for (int e = 0; e < 4; e++) acc[i][j][e] = 0.f;

    load_stage(sb, 0, 0, Ahi, Alo, Bhi, m0, n0, tid);
    CP_COMMIT();
    load_stage(sb, 1, 1, Ahi, Alo, Bhi, m0, n0, tid);
    CP_COMMIT();

    const int a_row = lane & 15;
    const int a_coff = (lane >> 4) * 8;
    const int b_row = (lane & 7) + ((lane >> 4) << 3);
    const int b_coff = ((lane >> 3) & 1) * 8;

    for (int kc = 0; kc < 1024 / BK; kc++) {
        CP_WAIT1();
        __syncthreads();
        const int stg = kc & 1;
        const uint32_t aHiB = sb + stg * STAGE_B;
        const uint32_t aLoB = aHiB + TILE_B;
        const uint32_t bHiB = aLoB + TILE_B;

#pragma unroll
        for (int ks = 0; ks < 2; ks++) {
            const int k0 = ks * 16;
            uint32_t ahi[4][4], alo[4][4];
#pragma unroll
            for (int mt = 0; mt < 4; mt++) {
                uint32_t off = (uint32_t)(((wm * 64 + mt * 16 + a_row) * PAD + k0 + a_coff) * 2);
                ldmx4(ahi[mt], aHiB + off);
                ldmx4(alo[mt], aLoB + off);
            }
            uint32_t bhi[2][4];
#pragma unroll
            for (int nt2 = 0; nt2 < 2; nt2++) {
                uint32_t off = (uint32_t)(((wn * 32 + nt2 * 16 + b_row) * PAD + k0 + b_coff) * 2);
                ldmx4(bhi[nt2], bHiB + off);
            }
#pragma unroll
            for (int mt = 0; mt < 4; mt++)
#pragma unroll
                for (int nt = 0; nt < 4; nt++) {
                    const uint32_t* bh = &bhi[nt >> 1][(nt & 1) * 2];
                    mma16816(acc[mt][nt], ahi[mt], bh);
                    mma16816(acc[mt][nt], alo[mt], bh);
                }
        }
        __syncthreads();
        if (kc + 2 < 1024 / BK)
            load_stage(sb, stg, kc + 2, Ahi, Alo, Bhi, m0, n0, tid);
        CP_COMMIT();
    }

    const int erow = lane >> 2, ecol = (lane & 3) * 2;
#pragma unroll
    for (int mt = 0; mt < 4; mt++)
#pragma unroll
        for (int nt = 0; nt < 4; nt++) {
            size_t r0 = (size_t)(m0 + wm * 64 + mt * 16 + erow);
            int    c0 = n0 + wn * 32 + nt * 8 + ecol;
            *(float2*)(C + r0 * 1024 + c0)       = make_float2(acc[mt][nt][0], acc[mt][nt][1]);
            *(float2*)(C + (r0 + 8) * 1024 + c0) = make_float2(acc[mt][nt][2], acc[mt][nt][3]);
        }
}

__global__ void __launch_bounds__(256, 1) tc_gemm_qkv() {
    const __half* bhi;
    float* C;
    if (blockIdx.z == 0)      { bhi = g_wqhi; C = g_q; }
    else if (blockIdx.z == 1) { bhi = g_wkhi; C = g_k; }
    else                      { bhi = g_wvhi; C = g_v; }
    tc_gemm_body(g_xhi, g_xlo, bhi, C);
}

__global__ void __launch_bounds__(256, 1) tc_gemm_out(float* __restrict__ out) {
    tc_gemm_body(g_yhi, g_ylo, g_wohi, out);
}

// ---------------------------------------------------------------------------
// RoPE + split: q -> (hi, lo) fp16; k -> hi fp16 only.
// ---------------------------------------------------------------------------
__global__ void rope_split_kernel(const int* __restrict__ tok,
                                  const int* __restrict__ use_rope,
                                  const float* __restrict__ cs,
                                  const float* __restrict__ sn) {
    int idx = blockIdx.x * blockDim.x + threadIdx.x;   // 0 .. 2*4096*512-1
    int t   = idx >> 21;
    int rp  = idx & ((1 << 21) - 1);
    int row = rp >> 9;
    int pp  = rp & 511;
    int h   = pp >> 5, j = pp & 31;
    int s   = row & (S_ - 1);
    float c = 1.f, si = 0.f;
    if (use_rope[0]) {
        int pos = tok[s];
        c  = cs[pos * 32 + j];
        si = sn[pos * 32 + j];
    }
    const float* T = t ? g_k : g_q;
    size_t off = (size_t)row * D_ + h * HD_ + 2 * j;
    float2 v = *(const float2*)(T + off);
    float rx = v.x * c - v.y * si;
    float ry = v.y * c + v.x * si;
    if (t) {
        *(ushort2*)((unsigned short*)g_khi + off) = make_ushort2(h16u(rx), h16u(ry));
    } else {
        *(ushort2*)((unsigned short*)g_qhi + off) = make_ushort2(h16u(rx), h16u(ry));
        *(ushort2*)((unsigned short*)g_qlo + off) =
            make_ushort2(h16u(rx - h16f(rx)), h16u(ry - h16f(ry)));
    }
}

// ---------------------------------------------------------------------------
// Flash attention, fp16 2-pass. Br=128, Bc=64, d=64. 256 threads = 8 warps.
// Q corrected (hi+lo), K/V hi only; P corrected in registers.
// Writes y directly as (hi, lo) fp16 for the output projection.
// ---------------------------------------------------------------------------
#define FPAD   72
#define QT_B   (128 * FPAD * 2)            // 18432 B per Q tile
#define KV_OFF (2 * QT_B)                  // 36864
#define KVT_B  (64 * FPAD * 2)             // 9216 B per K/V tile
#define FSTG_B (2 * KVT_B)                 // 18432 per stage (khi, vhi)
#define FLASH_SMEM (KV_OFF + 2 * FSTG_B)   // 73728 B

__device__ __forceinline__ void flash_load_kv(uint32_t sb, int stg, int kt,
                                              int b, int h, int tid) {
    uint32_t base = sb + KV_OFF + stg * FSTG_B;
    size_t krow0 = (size_t)(b * S_ + kt * 64);
    const __half* srcs[2] = {g_khi, g_vhi};
#pragma unroll
    for (int t = 0; t < 2; t++) {
#pragma unroll
        for (int it = 0; it < 2; it++) {
            int seg = it * 256 + tid;
            int r = seg >> 3, c8 = (seg & 7) * 8;
            cp16(base + t * KVT_B + (r * FPAD + c8) * 2,
                 srcs[t] + (krow0 + r) * 1024 + h * HD_ + c8);
        }
    }
}

__global__ void __launch_bounds__(256, 1) flash_mma_kernel() {
    extern __shared__ char fsm[];
    const uint32_t sb = smem_to_u32(fsm);
    const int tid = threadIdx.x, lane = tid & 31, warp = tid >> 5;
    const int qt = gridDim.x - 1 - blockIdx.x;   // heavy tiles first
    const int h = blockIdx.y, b = blockIdx.z;
    const int q0 = qt * 128;
    const size_t qrow0 = (size_t)(b * S_ + q0);
    const int nb = 2 * (qt + 1);

    // async-load Q tiles (hi, lo)
    {
        const __half* qs[2] = {g_qhi, g_qlo};
#pragma unroll
        for (int t = 0; t < 2; t++)
#pragma unroll
            for (int it = 0; it < 4; it++) {
                int seg = it * 256 + tid;
                int r = seg >> 3, c8 = (seg & 7) * 8;
                cp16(sb + t * QT_B + (r * FPAD + c8) * 2,
                     qs[t] + (qrow0 + r) * 1024 + h * HD_ + c8);
            }
    }
    CP_COMMIT();
    flash_load_kv(sb, 0, 0, b, h, tid);
    CP_COMMIT();
    flash_load_kv(sb, 1, 1, b, h, tid);
    CP_COMMIT();

    float oacc[8][4];
#pragma unroll
    for (int nt = 0; nt < 8; nt++)
#pragma unroll
        for (int e = 0; e < 4; e++) oacc[nt][e] = 0.f;
    float m_i[2] = {-1e30f, -1e30f}, l_i[2] = {0.f, 0.f};

    const int a_row = lane & 15;
    const int a_coff = (lane >> 4) * 8;
    const int b_row = (lane & 7) + ((lane >> 4) << 3);
    const int b_coff = ((lane >> 3) & 1) * 8;
    const int wm16 = warp * 16;
    const int vt = lane >> 3, vi = lane & 7;

    for (int kt = 0; kt < nb; kt++) {
        CP_WAIT1();
        __syncthreads();
        const uint32_t kb = sb + KV_OFF + (kt & 1) * FSTG_B;

        // ---- S = Q @ K^T (2-pass) ----
        float sacc[8][4];
#pragma unroll
        for (int nt = 0; nt < 8; nt++)
#pragma unroll
            for (int e = 0; e < 4; e++) sacc[nt][e] = 0.f;

#pragma unroll
        for (int ks = 0; ks < 4; ks++) {
            const int k0 = ks * 16;
            uint32_t aqh[4], aql[4];
            uint32_t qoff = (uint32_t)(((wm16 + a_row) * FPAD + k0 + a_coff) * 2);
            ldmx4(aqh, sb + qoff);
            ldmx4(aql, sb + QT_B + qoff);
            uint32_t bkh[4][4];
#pragma unroll
            for (int nt2 = 0; nt2 < 4; nt2++) {
                uint32_t off = (uint32_t)(((nt2 * 16 + b_row) * FPAD + k0 + b_coff) * 2);
                ldmx4(bkh[nt2], kb + off);
            }
#pragma unroll
            for (int nt = 0; nt < 8; nt++) {
                const uint32_t* bh = &bkh[nt >> 1][(nt & 1) * 2];
                mma16816(sacc[nt], aqh, bh);
                mma16816(sacc[nt], aql, bh);
            }
        }

        // ---- scale + causal mask + row max ----
        const int rbase = q0 + wm16 + (lane >> 2);
        const int cbase = kt * 64 + 2 * (lane & 3);
        float mt[2] = {-1e30f, -1e30f};
#pragma unroll
        for (int nt = 0; nt < 8; nt++)
#pragma unroll
            for (int e = 0; e < 4; e++) {
                int col = cbase + nt * 8 + (e & 1);
                int row = rbase + ((e >> 1) << 3);
                float sv = sacc[nt][e] * 0.125f;
                if (col > row) sv = -1e30f;
                sacc[nt][e] = sv;
                mt[e >> 1] = fmaxf(mt[e >> 1], sv);
            }
#pragma unroll
        for (int off = 1; off <= 2; off <<= 1)
#pragma unroll
            for (int rh = 0; rh < 2; rh++)
                mt[rh] = fmaxf(mt[rh], __shfl_xor_sync(0xffffffffu, mt[rh], off));

        float mn[2], alpha[2];
#pragma unroll
        for (int rh = 0; rh < 2; rh++) {
            mn[rh] = fmaxf(m_i[rh], mt[rh]);
            alpha[rh] = __expf(m_i[rh] - mn[rh]);
            m_i[rh] = mn[rh];
        }

        // ---- exp + split P to fp16 hi/lo packed frags ----
        uint32_t phi[8][2], plo[8][2];
        float psum[2] = {0.f, 0.f};
#pragma unroll
        for (int nt = 0; nt < 8; nt++) {
#pragma unroll
            for (int hf = 0; hf < 2; hf++) {
                float p0 = __expf(sacc[nt][hf * 2]     - mn[hf]);
                float p1 = __expf(sacc[nt][hf * 2 + 1] - mn[hf]);
                psum[hf] += p0 + p1;
                uint16_t h0 = h16u(p0), h1 = h16u(p1);
                phi[nt][hf] = (uint32_t)h0 | ((uint32_t)h1 << 16);
                uint16_t l0 = h16u(p0 - h16f(p0)), l1 = h16u(p1 - h16f(p1));
                plo[nt][hf] = (uint32_t)l0 | ((uint32_t)l1 << 16);
            }
        }
#pragma unroll
        for (int off = 1; off <= 2; off <<= 1)
#pragma unroll
            for (int rh = 0; rh < 2; rh++)
                psum[rh] += __shfl_xor_sync(0xffffffffu, psum[rh], off);
#pragma unroll
        for (int rh = 0; rh < 2; rh++)
            l_i[rh] = l_i[rh] * alpha[rh] + psum[rh];

        // rescale O
#pragma unroll
        for (int nt = 0; nt < 8; nt++) {
            oacc[nt][0] *= alpha[0]; oacc[nt][1] *= alpha[0];
            oacc[nt][2] *= alpha[1]; oacc[nt][3] *= alpha[1];
        }

        // ---- O += P @ V (2-pass), V via ldmatrix.trans ----
#pragma unroll
        for (int ks = 0; ks < 4; ks++) {
            uint32_t pah[4] = {phi[2*ks][0], phi[2*ks][1], phi[2*ks+1][0], phi[2*ks+1][1]};
            uint32_t pal[4] = {plo[2*ks][0], plo[2*ks][1], plo[2*ks+1][0], plo[2*ks+1][1]};
#pragma unroll
            for (int ntp = 0; ntp < 4; ntp++) {
                uint32_t vaddr = kb + KVT_B +
                    (uint32_t)(((ks * 16 + (vt & 1) * 8 + vi) * FPAD + ntp * 16 + (vt >> 1) * 8) * 2);
                uint32_t vh[4];
                ldmx4t(vh, vaddr);
                mma16816(oacc[2*ntp],   pah, &vh[0]);
                mma16816(oacc[2*ntp],   pal, &vh[0]);
                mma16816(oacc[2*ntp+1], pah, &vh[2]);
                mma16816(oacc[2*ntp+1], pal, &vh[2]);
            }
        }

        __syncthreads();
        if (kt + 2 < nb)
            flash_load_kv(sb, kt & 1, kt + 2, b, h, tid);
        CP_COMMIT();
    }

    // ---- epilogue: write y as (hi, lo) fp16 directly ----
    float inv0 = 1.f / l_i[0], inv1 = 1.f / l_i[1];
    size_t row0 = qrow0 + wm16 + (lane >> 2);
    int colb = h * HD_ + 2 * (lane & 3);
    unsigned short* yh = (unsigned short*)g_yhi;
    unsigned short* yl = (unsigned short*)g_ylo;
#pragma unroll
    for (int nt = 0; nt < 8; nt++) {
        int col = colb + nt * 8;
        float v0 = oacc[nt][0] * inv0, v1 = oacc[nt][1] * inv0;
        float v2 = oacc[nt][2] * inv1, v3 = oacc[nt][3] * inv1;
        *(ushort2*)(yh + row0 * 1024 + col) = make_ushort2(h16u(v0), h16u(v1));
        *(ushort2*)(yl + row0 * 1024 + col) =
            make_ushort2(h16u(v0 - h16f(v0)), h16u(v1 - h16f(v1)));
        *(ushort2*)(yh + (row0 + 8) * 1024 + col) = make_ushort2(h16u(v2), h16u(v3));
        *(ushort2*)(yl + (row0 + 8) * 1024 + col) =
            make_ushort2(h16u(v2 - h16f(v2)), h16u(v3 - h16f(v3)));
    }
}

// ---------------------------------------------------------------------------
extern "C" void kernel_launch(void* const* d_in, const int* in_sizes, int n_in,
                              void* d_out, int out_size) {
    const float* x        = (const float*)d_in[0];
    const int*   tok      = (const int*)  d_in[1];
    const int*   use_rope = (const int*)  d_in[2];
    const float* Wq       = (const float*)d_in[3];
    const float* Wk       = (const float*)d_in[4];
    const float* Wv       = (const float*)d_in[5];
    const float* Wo       = (const float*)d_in[6];
    const float* cs       = (const float*)d_in[7];
    const float* sn       = (const float*)d_in[8];
    float* out = (float*)d_out;

    void *p_xhi, *p_xlo, *p_v, *p_vhi;
    void *p_wqhi, *p_wkhi, *p_wvhi, *p_wohi;
    cudaGetSymbolAddress(&p_xhi, g_xhi);   cudaGetSymbolAddress(&p_xlo, g_xlo);
    cudaGetSymbolAddress(&p_v,   g_v);     cudaGetSymbolAddress(&p_vhi, g_vhi);
    cudaGetSymbolAddress(&p_wqhi, g_wqhi); cudaGetSymbolAddress(&p_wkhi, g_wkhi);
    cudaGetSymbolAddress(&p_wvhi, g_wvhi); cudaGetSymbolAddress(&p_wohi, g_wohi);

    cudaFuncSetAttribute(tc_gemm_qkv, cudaFuncAttributeMaxDynamicSharedMemorySize, GEMM_SMEM);
    cudaFuncSetAttribute(tc_gemm_out, cudaFuncAttributeMaxDynamicSharedMemorySize, GEMM_SMEM);
    cudaFuncSetAttribute(flash_mma_kernel, cudaFuncAttributeMaxDynamicSharedMemorySize, FLASH_SMEM);

    const int nx4 = (B_*S_*D_) / 4;
    const int nw4 = (D_*D_) / 4;

    split2_kernel<<<(nx4 + 255) / 256, 256>>>(x,  (__half*)p_xhi, (__half*)p_xlo, nx4);
    split1_kernel<<<(nw4 + 255) / 256, 256>>>(Wq, (__half*)p_wqhi, nw4);
    split1_kernel<<<(nw4 + 255) / 256, 256>>>(Wk, (__half*)p_wkhi, nw4);
    split1_kernel<<<(nw4 + 255) / 256, 256>>>(Wv, (__half*)p_wvhi, nw4);
    split1_kernel<<<(nw4 + 255) / 256, 256>>>(Wo, (__half*)p_wohi, nw4);

    tc_gemm_qkv<<<dim3(8, 32, 3), 256, GEMM_SMEM>>>();

    rope_split_kernel<<<(2u * B_ * S_ * (D_ / 2)) / 256u, 256>>>(tok, use_rope, cs, sn);
    split1_kernel<<<(nx4 + 255) / 256, 256>>>((const float*)p_v, (__half*)p_vhi, nx4);

    flash_mma_kernel<<<dim3(S_ / 128, H_, B_), 256, FLASH_SMEM>>>();

    tc_gemm_out<<<dim3(8, 32), 256, GEMM_SMEM>>>(out);
}

// round 6
// speedup vs baseline: 3.8024x; 1.0099x over previous
#include <cuda_runtime.h>
#include <cuda_fp16.h>
#include <math_constants.h>
#include <cstdint>

#define B_  2
#define S_  2048
#define D_  1024
#define H_  16
#define HD_ 64

// ---------------------------------------------------------------------------
// Scratch (__device__ globals; allocation-free rule)
// ---------------------------------------------------------------------------
__device__ __align__(16) __half g_xhi[B_*S_*D_], g_xlo[B_*S_*D_];
__device__ __align__(16) __half g_yhi[B_*S_*D_], g_ylo[B_*S_*D_];
__device__ __align__(16) __half g_qhi[B_*S_*D_], g_qlo[B_*S_*D_];
__device__ __align__(16) __half g_khi[B_*S_*D_];
__device__ __align__(16) __half g_vhi[B_*S_*D_];
__device__ __align__(16) __half g_wqhi[D_*D_];
__device__ __align__(16) __half g_wkhi[D_*D_];
__device__ __align__(16) __half g_wvhi[D_*D_];
__device__ __align__(16) __half g_wohi[D_*D_];

// ---------------------------------------------------------------------------
// Low-level helpers (base-target instructions only)
// ---------------------------------------------------------------------------
__device__ __forceinline__ uint32_t smem_to_u32(const void* p) {
    uint32_t a;
    asm("{ .reg .u64 t; cvta.to.shared.u64 t, %1; cvt.u32.u64 %0, t; }" : "=r"(a) : "l"(p));
    return a;
}

__device__ __forceinline__ void cp16(uint32_t saddr, const void* gaddr) {
    asm volatile("cp.async.cg.shared.global [%0], [%1], 16;" :: "r"(saddr), "l"(gaddr));
}
#define CP_COMMIT() asm volatile("cp.async.commit_group;" ::: "memory")
#define CP_WAIT1()  asm volatile("cp.async.wait_group 1;"  ::: "memory")

__device__ __forceinline__ void ldmx4(uint32_t* r, uint32_t addr) {
    asm volatile("ldmatrix.sync.aligned.m8n8.x4.shared.b16 {%0,%1,%2,%3}, [%4];"
        : "=r"(r[0]), "=r"(r[1]), "=r"(r[2]), "=r"(r[3]) : "r"(addr));
}
__device__ __forceinline__ void ldmx4t(uint32_t* r, uint32_t addr) {
    asm volatile("ldmatrix.sync.aligned.m8n8.x4.trans.shared.b16 {%0,%1,%2,%3}, [%4];"
        : "=r"(r[0]), "=r"(r[1]), "=r"(r[2]), "=r"(r[3]) : "r"(addr));
}

__device__ __forceinline__ void mma16816(float* c, const uint32_t* a, const uint32_t* b) {
    asm volatile(
        "mma.sync.aligned.m16n8k16.row.col.f32.f16.f16.f32 "
        "{%0,%1,%2,%3}, {%4,%5,%6,%7}, {%8,%9}, {%0,%1,%2,%3};"
        : "+f"(c[0]), "+f"(c[1]), "+f"(c[2]), "+f"(c[3])
        : "r"(a[0]), "r"(a[1]), "r"(a[2]), "r"(a[3]), "r"(b[0]), "r"(b[1]));
}

__device__ __forceinline__ uint16_t h16u(float f) { return __half_as_ushort(__float2half(f)); }
__device__ __forceinline__ float    h16f(float f) { return __half2float(__float2half(f)); }
__device__ __forceinline__ uint32_t pack2(float a, float b) {
    return (uint32_t)h16u(a) | ((uint32_t)h16u(b) << 16);
}

// ---------------------------------------------------------------------------
// Splits
// ---------------------------------------------------------------------------
__global__ void split2_kernel(const float* __restrict__ src,
                              __half* __restrict__ hi,
                              __half* __restrict__ lo, int n4) {
    int i = blockIdx.x * blockDim.x + threadIdx.x;
    if (i >= n4) return;
    float4 v = ((const float4*)src)[i];
    float vv[4] = {v.x, v.y, v.z, v.w};
    unsigned short hs[4], ls[4];
#pragma unroll
    for (int j = 0; j < 4; j++) {
        float hf = h16f(vv[j]);
        hs[j] = h16u(vv[j]);
        ls[j] = h16u(vv[j] - hf);
    }
    ((ushort4*)hi)[i] = make_ushort4(hs[0], hs[1], hs[2], hs[3]);
    ((ushort4*)lo)[i] = make_ushort4(ls[0], ls[1], ls[2], ls[3]);
}

// One launch converts all 4 weight matrices (blockIdx.y selects).
__global__ void split1w_kernel(const float* __restrict__ w0, const float* __restrict__ w1,
                               const float* __restrict__ w2, const float* __restrict__ w3,
                               int n4) {
    int i = blockIdx.x * blockDim.x + threadIdx.x;
    if (i >= n4) return;
    const float* src;
    __half* dst;
    switch (blockIdx.y) {
        case 0: src = w0; dst = g_wqhi; break;
        case 1: src = w1; dst = g_wkhi; break;
        case 2: src = w2; dst = g_wvhi; break;
        default: src = w3; dst = g_wohi; break;
    }
    float4 v = ((const float4*)src)[i];
    ((ushort4*)dst)[i] = make_ushort4(h16u(v.x), h16u(v.y), h16u(v.z), h16u(v.w));
}

// ---------------------------------------------------------------------------
// fp16 2-pass GEMM mainloop: acc = A @ B^T on a 128x128 tile, K=1024.
// 128x128 CTA tile, BK=32, 256 threads (8 warps 2x4), warp tile 64x32.
// ---------------------------------------------------------------------------
#define BK     32
#define PAD    40
#define TILE_B (128 * PAD * 2)          // 10240 B
#define STAGE_B (3 * TILE_B)            // Ahi, Alo, Bhi = 30720 B
#define GEMM_SMEM (2 * STAGE_B)         // 61440 B

__device__ __forceinline__ void load_stage(uint32_t sb, int stg, int kc,
        const __half* __restrict__ Ahi, const __half* __restrict__ Alo,
        const __half* __restrict__ Bhi,
        int m0, int n0, int tid) {
    const __half* srcs[3] = {Ahi, Alo, Bhi};
    const int r0s[3] = {m0, m0, n0};
    uint32_t base = sb + stg * STAGE_B;
#pragma unroll
    for (int t = 0; t < 3; t++) {
        const __half* src = srcs[t];
        const int r0 = r0s[t];
        uint32_t tb = base + t * TILE_B;
#pragma unroll
        for (int it = 0; it < 2; it++) {
            int seg = it * 256 + tid;
            int r = seg >> 2, c8 = (seg & 3) * 8;
            cp16(tb + (r * PAD + c8) * 2,
                 src + (size_t)(r0 + r) * 1024 + kc * BK + c8);
        }
    }
}

__device__ __forceinline__ void tc_gemm_mainloop(
        const __half* __restrict__ Ahi, const __half* __restrict__ Alo,
        const __half* __restrict__ Bhi,
        int m0, int n0, float acc[4][4][4]) {
    extern __shared__ char smem[];
    const uint32_t sb = smem_to_u32(smem);
    const int tid = threadIdx.x, lane = tid & 31, warp = tid >> 5;
    const int wm = warp >> 2, wn = warp & 3;

#pragma unroll
    for (int i = 0; i < 4; i++)
#pragma unroll
        for (int j = 0; j < 4; j++)
#pragma unroll
            for (int e = 0; e < 4; e++) acc[i][j][e] = 0.f;

    load_stage(sb, 0, 0, Ahi, Alo, Bhi, m0, n0, tid);
    CP_COMMIT();
    load_stage(sb, 1, 1, Ahi, Alo, Bhi, m0, n0, tid);
    CP_COMMIT();

    const int a_row = lane & 15;
    const int a_coff = (lane >> 4) * 8;
    const int b_row = (lane & 7) + ((lane >> 4) << 3);
    const int b_coff = ((lane >> 3) & 1) * 8;

    for (int kc = 0; kc < 1024 / BK; kc++) {
        CP_WAIT1();
        __syncthreads();
        const int stg = kc & 1;
        const uint32_t aHiB = sb + stg * STAGE_B;
        const uint32_t aLoB = aHiB + TILE_B;
        const uint32_t bHiB = aLoB + TILE_B;

#pragma unroll
        for (int ks = 0; ks < 2; ks++) {
            const int k0 = ks * 16;
            uint32_t ahi[4][4], alo[4][4];
#pragma unroll
            for (int mt = 0; mt < 4; mt++) {
                uint32_t off = (uint32_t)(((wm * 64 + mt * 16 + a_row) * PAD + k0 + a_coff) * 2);
                ldmx4(ahi[mt], aHiB + off);
                ldmx4(alo[mt], aLoB + off);
            }
            uint32_t bhi[2][4];
#pragma unroll
            for (int nt2 = 0; nt2 < 2; nt2++) {
                uint32_t off = (uint32_t)(((wn * 32 + nt2 * 16 + b_row) * PAD + k0 + b_coff) * 2);
                ldmx4(bhi[nt2], bHiB + off);
            }
#pragma unroll
            for (int mt = 0; mt < 4; mt++)
#pragma unroll
                for (int nt = 0; nt < 4; nt++) {
                    const uint32_t* bh = &bhi[nt >> 1][(nt & 1) * 2];
                    mma16816(acc[mt][nt], ahi[mt], bh);
                    mma16816(acc[mt][nt], alo[mt], bh);
                }
        }
        __syncthreads();
        if (kc + 2 < 1024 / BK)
            load_stage(sb, stg, kc + 2, Ahi, Alo, Bhi, m0, n0, tid);
        CP_COMMIT();
    }
}

// ---------------------------------------------------------------------------
// QKV GEMM with fused RoPE + fp16 split epilogue.
// z=0: Q -> rope -> (qhi, qlo); z=1: K -> rope -> khi; z=2: V -> vhi.
// ---------------------------------------------------------------------------
__global__ void __launch_bounds__(256, 2) tc_gemm_qkv(
        const int* __restrict__ tok, const int* __restrict__ use_rope,
        const float* __restrict__ cs, const float* __restrict__ sn) {
    const int z = blockIdx.z;
    const __half* bhi = (z == 0) ? g_wqhi : (z == 1) ? g_wkhi : g_wvhi;
    const int m0 = blockIdx.y * 128, n0 = blockIdx.x * 128;

    float acc[4][4][4];
    tc_gemm_mainloop(g_xhi, g_xlo, bhi, m0, n0, acc);

    const int lane = threadIdx.x & 31, warp = threadIdx.x >> 5;
    const int wm = warp >> 2, wn = warp & 3;
    const int erow = lane >> 2, ecol = (lane & 3) * 2;
    const int ur = (z < 2) ? use_rope[0] : 0;

    unsigned short* dhi = (z == 0) ? (unsigned short*)g_qhi :
                          (z == 1) ? (unsigned short*)g_khi : (unsigned short*)g_vhi;
    unsigned short* dlo = (unsigned short*)g_qlo;

#pragma unroll
    for (int mt = 0; mt < 4; mt++)
#pragma unroll
        for (int nt = 0; nt < 4; nt++) {
            const int c0 = n0 + wn * 32 + nt * 8 + ecol;   // even
            const int j = (c0 & 63) >> 1;
#pragma unroll
            for (int hf = 0; hf < 2; hf++) {
                const int r = m0 + wm * 64 + mt * 16 + erow + hf * 8;
                float v0 = acc[mt][nt][hf * 2];
                float v1 = acc[mt][nt][hf * 2 + 1];
                float rx = v0, ry = v1;
                if (ur) {
                    int pos = tok[r & (S_ - 1)];
                    float c  = cs[pos * 32 + j];
                    float si = sn[pos * 32 + j];
                    rx = v0 * c - v1 * si;
                    ry = v1 * c + v0 * si;
                }
                size_t off = (size_t)r * 1024 + c0;
                *(ushort2*)(dhi + off) = make_ushort2(h16u(rx), h16u(ry));
                if (z == 0)
                    *(ushort2*)(dlo + off) =
                        make_ushort2(h16u(rx - h16f(rx)), h16u(ry - h16f(ry)));
            }
        }
}

// ---------------------------------------------------------------------------
// Output GEMM: fp32 epilogue to d_out.
// ---------------------------------------------------------------------------
__global__ void __launch_bounds__(256, 2) tc_gemm_out(float* __restrict__ out) {
    const int m0 = blockIdx.y * 128, n0 = blockIdx.x * 128;
    float acc[4][4][4];
    tc_gemm_mainloop(g_yhi, g_ylo, g_wohi, m0, n0, acc);

    const int lane = threadIdx.x & 31, warp = threadIdx.x >> 5;
    const int wm = warp >> 2, wn = warp & 3;
    const int erow = lane >> 2, ecol = (lane & 3) * 2;
#pragma unroll
    for (int mt = 0; mt < 4; mt++)
#pragma unroll
        for (int nt = 0; nt < 4; nt++) {
            size_t r0 = (size_t)(m0 + wm * 64 + mt * 16 + erow);
            int    c0 = n0 + wn * 32 + nt * 8 + ecol;
            *(float2*)(out + r0 * 1024 + c0)       = make_float2(acc[mt][nt][0], acc[mt][nt][1]);
            *(float2*)(out + (r0 + 8) * 1024 + c0) = make_float2(acc[mt][nt][2], acc[mt][nt][3]);
        }
}

// ---------------------------------------------------------------------------
// Flash attention, fp16 2-pass, Br=128, Bc=64, d=64, 256 threads = 8 warps.
// ---------------------------------------------------------------------------
#define FPAD   72
#define QT_B   (128 * FPAD * 2)
#define KV_OFF (2 * QT_B)
#define KVT_B  (64 * FPAD * 2)
#define FSTG_B (2 * KVT_B)
#define FLASH_SMEM (KV_OFF + 2 * FSTG_B)   // 73728 B

__device__ __forceinline__ void flash_load_kv(uint32_t sb, int stg, int kt,
                                              int b, int h, int tid) {
    uint32_t base = sb + KV_OFF + stg * FSTG_B;
    size_t krow0 = (size_t)(b * S_ + kt * 64);
    const __half* srcs[2] = {g_khi, g_vhi};
#pragma unroll
    for (int t = 0; t < 2; t++) {
#pragma unroll
        for (int it = 0; it < 2; it++) {
            int seg = it * 256 + tid;
            int r = seg >> 3, c8 = (seg & 7) * 8;
            cp16(base + t * KVT_B + (r * FPAD + c8) * 2,
                 srcs[t] + (krow0 + r) * 1024 + h * HD_ + c8);
        }
    }
}

__global__ void __launch_bounds__(256, 2) flash_mma_kernel() {
    extern __shared__ char fsm[];
    const uint32_t sb = smem_to_u32(fsm);
    const int tid = threadIdx.x, lane = tid & 31, warp = tid >> 5;
    const int qt = gridDim.x - 1 - blockIdx.x;   // heavy tiles first
    const int h = blockIdx.y, b = blockIdx.z;
    const int q0 = qt * 128;
    const size_t qrow0 = (size_t)(b * S_ + q0);
    const int nb = 2 * (qt + 1);

    {
        const __half* qs[2] = {g_qhi, g_qlo};
#pragma unroll
        for (int t = 0; t < 2; t++)
#pragma unroll
            for (int it = 0; it < 4; it++) {
                int seg = it * 256 + tid;
                int r = seg >> 3, c8 = (seg & 7) * 8;
                cp16(sb + t * QT_B + (r * FPAD + c8) * 2,
                     qs[t] + (qrow0 + r) * 1024 + h * HD_ + c8);
            }
    }
    CP_COMMIT();
    flash_load_kv(sb, 0, 0, b, h, tid);
    CP_COMMIT();
    flash_load_kv(sb, 1, 1, b, h, tid);
    CP_COMMIT();

    float oacc[8][4];
#pragma unroll
    for (int nt = 0; nt < 8; nt++)
#pragma unroll
        for (int e = 0; e < 4; e++) oacc[nt][e] = 0.f;
    float m_i[2] = {-1e30f, -1e30f}, l_i[2] = {0.f, 0.f};

    const int a_row = lane & 15;
    const int a_coff = (lane >> 4) * 8;
    const int b_row = (lane & 7) + ((lane >> 4) << 3);
    const int b_coff = ((lane >> 3) & 1) * 8;
    const int wm16 = warp * 16;
    const int vt = lane >> 3, vi = lane & 7;

    for (int kt = 0; kt < nb; kt++) {
        CP_WAIT1();
        __syncthreads();
        const uint32_t kb = sb + KV_OFF + (kt & 1) * FSTG_B;

        // ---- S = Q @ K^T (2-pass) ----
        float sacc[8][4];
#pragma unroll
        for (int nt = 0; nt < 8; nt++)
#pragma unroll
            for (int e = 0; e < 4; e++) sacc[nt][e] = 0.f;

#pragma unroll
        for (int ks = 0; ks < 4; ks++) {
            const int k0 = ks * 16;
            uint32_t aqh[4], aql[4];
            uint32_t qoff = (uint32_t)(((wm16 + a_row) * FPAD + k0 + a_coff) * 2);
            ldmx4(aqh, sb + qoff);
            ldmx4(aql, sb + QT_B + qoff);
            uint32_t bkh[4][4];
#pragma unroll
            for (int nt2 = 0; nt2 < 4; nt2++) {
                uint32_t off = (uint32_t)(((nt2 * 16 + b_row) * FPAD + k0 + b_coff) * 2);
                ldmx4(bkh[nt2], kb + off);
            }
#pragma unroll
            for (int nt = 0; nt < 8; nt++) {
                const uint32_t* bh = &bkh[nt >> 1][(nt & 1) * 2];
                mma16816(sacc[nt], aqh, bh);
                mma16816(sacc[nt], aql, bh);
            }
        }

        // ---- scale + causal mask + row max ----
        const int rbase = q0 + wm16 + (lane >> 2);
        const int cbase = kt * 64 + 2 * (lane & 3);
        float mt[2] = {-1e30f, -1e30f};
#pragma unroll
        for (int nt = 0; nt < 8; nt++)
#pragma unroll
            for (int e = 0; e < 4; e++) {
                int col = cbase + nt * 8 + (e & 1);
                int row = rbase + ((e >> 1) << 3);
                float sv = sacc[nt][e] * 0.125f;
                if (col > row) sv = -1e30f;
                sacc[nt][e] = sv;
                mt[e >> 1] = fmaxf(mt[e >> 1], sv);
            }
#pragma unroll
        for (int off = 1; off <= 2; off <<= 1)
#pragma unroll
            for (int rh = 0; rh < 2; rh++)
                mt[rh] = fmaxf(mt[rh], __shfl_xor_sync(0xffffffffu, mt[rh], off));

        float mn[2], alpha[2];
#pragma unroll
        for (int rh = 0; rh < 2; rh++) {
            mn[rh] = fmaxf(m_i[rh], mt[rh]);
            alpha[rh] = __expf(m_i[rh] - mn[rh]);
            m_i[rh] = mn[rh];
        }

        // ---- exp in place + partial sums ----
        float psum[2] = {0.f, 0.f};
#pragma unroll
        for (int nt = 0; nt < 8; nt++)
#pragma unroll
            for (int hf = 0; hf < 2; hf++) {
                float p0 = __expf(sacc[nt][hf * 2]     - mn[hf]);
                float p1 = __expf(sacc[nt][hf * 2 + 1] - mn[hf]);
                psum[hf] += p0 + p1;
                sacc[nt][hf * 2]     = p0;
                sacc[nt][hf * 2 + 1] = p1;
            }
#pragma unroll
        for (int off = 1; off <= 2; off <<= 1)
#pragma unroll
            for (int rh = 0; rh < 2; rh++)
                psum[rh] += __shfl_xor_sync(0xffffffffu, psum[rh], off);
#pragma unroll
        for (int rh = 0; rh < 2; rh++)
            l_i[rh] = l_i[rh] * alpha[rh] + psum[rh];

#pragma unroll
        for (int nt = 0; nt < 8; nt++) {
            oacc[nt][0] *= alpha[0]; oacc[nt][1] *= alpha[0];
            oacc[nt][2] *= alpha[1]; oacc[nt][3] *= alpha[1];
        }

        // ---- O += P @ V (2-pass); pack P per-ks (no persistent frags) ----
#pragma unroll
        for (int ks = 0; ks < 4; ks++) {
            const float* s0 = sacc[2 * ks];
            const float* s1 = sacc[2 * ks + 1];
            uint32_t pah[4], pal[4];
            pah[0] = pack2(s0[0], s0[1]); pah[1] = pack2(s0[2], s0[3]);
            pah[2] = pack2(s1[0], s1[1]); pah[3] = pack2(s1[2], s1[3]);
            pal[0] = pack2(s0[0] - h16f(s0[0]), s0[1] - h16f(s0[1]));
            pal[1] = pack2(s0[2] - h16f(s0[2]), s0[3] - h16f(s0[3]));
            pal[2] = pack2(s1[0] - h16f(s1[0]), s1[1] - h16f(s1[1]));
            pal[3] = pack2(s1[2] - h16f(s1[2]), s1[3] - h16f(s1[3]));
#pragma unroll
            for (int ntp = 0; ntp < 4; ntp++) {
                uint32_t vaddr = kb + KVT_B +
                    (uint32_t)(((ks * 16 + (vt & 1) * 8 + vi) * FPAD + ntp * 16 + (vt >> 1) * 8) * 2);
                uint32_t vh[4];
                ldmx4t(vh, vaddr);
                mma16816(oacc[2*ntp],   pah, &vh[0]);
                mma16816(oacc[2*ntp],   pal, &vh[0]);
                mma16816(oacc[2*ntp+1], pah, &vh[2]);
                mma16816(oacc[2*ntp+1], pal, &vh[2]);
            }
        }

        __syncthreads();
        if (kt + 2 < nb)
            flash_load_kv(sb, kt & 1, kt + 2, b, h, tid);
        CP_COMMIT();
    }

    // ---- epilogue: y as (hi, lo) fp16 ----
    float inv0 = 1.f / l_i[0], inv1 = 1.f / l_i[1];
    size_t row0 = qrow0 + wm16 + (lane >> 2);
    int colb = h * HD_ + 2 * (lane & 3);
    unsigned short* yh = (unsigned short*)g_yhi;
    unsigned short* yl = (unsigned short*)g_ylo;
#pragma unroll
    for (int nt = 0; nt < 8; nt++) {
        int col = colb + nt * 8;
        float v0 = oacc[nt][0] * inv0, v1 = oacc[nt][1] * inv0;
        float v2 = oacc[nt][2] * inv1, v3 = oacc[nt][3] * inv1;
        *(ushort2*)(yh + row0 * 1024 + col) = make_ushort2(h16u(v0), h16u(v1));
        *(ushort2*)(yl + row0 * 1024 + col) =
            make_ushort2(h16u(v0 - h16f(v0)), h16u(v1 - h16f(v1)));
        *(ushort2*)(yh + (row0 + 8) * 1024 + col) = make_ushort2(h16u(v2), h16u(v3));
        *(ushort2*)(yl + (row0 + 8) * 1024 + col) =
            make_ushort2(h16u(v2 - h16f(v2)), h16u(v3 - h16f(v3)));
    }
}

// ---------------------------------------------------------------------------
extern "C" void kernel_launch(void* const* d_in, const int* in_sizes, int n_in,
                              void* d_out, int out_size) {
    const float* x        = (const float*)d_in[0];
    const int*   tok      = (const int*)  d_in[1];
    const int*   use_rope = (const int*)  d_in[2];
    const float* Wq       = (const float*)d_in[3];
    const float* Wk       = (const float*)d_in[4];
    const float* Wv       = (const float*)d_in[5];
    const float* Wo       = (const float*)d_in[6];
    const float* cs       = (const float*)d_in[7];
    const float* sn       = (const float*)d_in[8];
    float* out = (float*)d_out;

    void *p_xhi, *p_xlo;
    cudaGetSymbolAddress(&p_xhi, g_xhi);
    cudaGetSymbolAddress(&p_xlo, g_xlo);

    cudaFuncSetAttribute(tc_gemm_qkv, cudaFuncAttributeMaxDynamicSharedMemorySize, GEMM_SMEM);
    cudaFuncSetAttribute(tc_gemm_out, cudaFuncAttributeMaxDynamicSharedMemorySize, GEMM_SMEM);
    cudaFuncSetAttribute(flash_mma_kernel, cudaFuncAttributeMaxDynamicSharedMemorySize, FLASH_SMEM);

    const int nx4 = (B_*S_*D_) / 4;
    const int nw4 = (D_*D_) / 4;

    split2_kernel<<<(nx4 + 255) / 256, 256>>>(x, (__half*)p_xhi, (__half*)p_xlo, nx4);
    split1w_kernel<<<dim3((nw4 + 255) / 256, 4), 256>>>(Wq, Wk, Wv, Wo, nw4);

    tc_gemm_qkv<<<dim3(8, 32, 3), 256, GEMM_SMEM>>>(tok, use_rope, cs, sn);

    flash_mma_kernel<<<dim3(S_ / 128, H_, B_), 256, FLASH_SMEM>>>();

    tc_gemm_out<<<dim3(8, 32), 256, GEMM_SMEM>>>(out);
}

// round 7
// speedup vs baseline: 4.4624x; 1.1736x over previous
#include <cuda_runtime.h>
#include <cuda_fp16.h>
#include <math_constants.h>
#include <cstdint>

#define B_  2
#define S_  2048
#define D_  1024
#define H_  16
#define HD_ 64

// ---------------------------------------------------------------------------
// Scratch (__device__ globals; allocation-free rule)
// ---------------------------------------------------------------------------
__device__ __align__(16) __half g_xhi[B_*S_*D_], g_xlo[B_*S_*D_];
__device__ __align__(16) __half g_yhi[B_*S_*D_];
__device__ __align__(16) __half g_qhi[B_*S_*D_], g_qlo[B_*S_*D_];
__device__ __align__(16) __half g_khi[B_*S_*D_];
__device__ __align__(16) __half g_vhi[B_*S_*D_];
__device__ __align__(16) __half g_wqhi[D_*D_];
__device__ __align__(16) __half g_wkhi[D_*D_];
__device__ __align__(16) __half g_wvhi[D_*D_];
__device__ __align__(16) __half g_wohi[D_*D_];

// ---------------------------------------------------------------------------
// Low-level helpers (base-target instructions only)
// ---------------------------------------------------------------------------
__device__ __forceinline__ uint32_t smem_to_u32(const void* p) {
    uint32_t a;
    asm("{ .reg .u64 t; cvta.to.shared.u64 t, %1; cvt.u32.u64 %0, t; }" : "=r"(a) : "l"(p));
    return a;
}

__device__ __forceinline__ void cp16(uint32_t saddr, const void* gaddr) {
    asm volatile("cp.async.cg.shared.global [%0], [%1], 16;" :: "r"(saddr), "l"(gaddr));
}
#define CP_COMMIT() asm volatile("cp.async.commit_group;" ::: "memory")
#define CP_WAIT1()  asm volatile("cp.async.wait_group 1;"  ::: "memory")

__device__ __forceinline__ void ldmx4(uint32_t* r, uint32_t addr) {
    asm volatile("ldmatrix.sync.aligned.m8n8.x4.shared.b16 {%0,%1,%2,%3}, [%4];"
        : "=r"(r[0]), "=r"(r[1]), "=r"(r[2]), "=r"(r[3]) : "r"(addr));
}
__device__ __forceinline__ void ldmx4t(uint32_t* r, uint32_t addr) {
    asm volatile("ldmatrix.sync.aligned.m8n8.x4.trans.shared.b16 {%0,%1,%2,%3}, [%4];"
        : "=r"(r[0]), "=r"(r[1]), "=r"(r[2]), "=r"(r[3]) : "r"(addr));
}

__device__ __forceinline__ void mma16816(float* c, const uint32_t* a, const uint32_t* b) {
    asm volatile(
        "mma.sync.aligned.m16n8k16.row.col.f32.f16.f16.f32 "
        "{%0,%1,%2,%3}, {%4,%5,%6,%7}, {%8,%9}, {%0,%1,%2,%3};"
        : "+f"(c[0]), "+f"(c[1]), "+f"(c[2]), "+f"(c[3])
        : "r"(a[0]), "r"(a[1]), "r"(a[2]), "r"(a[3]), "r"(b[0]), "r"(b[1]));
}

__device__ __forceinline__ uint16_t h16u(float f) { return __half_as_ushort(__float2half(f)); }
__device__ __forceinline__ float    h16f(float f) { return __half2float(__float2half(f)); }
__device__ __forceinline__ uint32_t pack2(float a, float b) {
    return (uint32_t)h16u(a) | ((uint32_t)h16u(b) << 16);
}

// ---------------------------------------------------------------------------
// Splits
// ---------------------------------------------------------------------------
__global__ void split2_kernel(const float* __restrict__ src,
                              __half* __restrict__ hi,
                              __half* __restrict__ lo, int n4) {
    int i = blockIdx.x * blockDim.x + threadIdx.x;
    if (i >= n4) return;
    float4 v = ((const float4*)src)[i];
    float vv[4] = {v.x, v.y, v.z, v.w};
    unsigned short hs[4], ls[4];
#pragma unroll
    for (int j = 0; j < 4; j++) {
        float hf = h16f(vv[j]);
        hs[j] = h16u(vv[j]);
        ls[j] = h16u(vv[j] - hf);
    }
    ((ushort4*)hi)[i] = make_ushort4(hs[0], hs[1], hs[2], hs[3]);
    ((ushort4*)lo)[i] = make_ushort4(ls[0], ls[1], ls[2], ls[3]);
}

__global__ void split1w_kernel(const float* __restrict__ w0, const float* __restrict__ w1,
                               const float* __restrict__ w2, const float* __restrict__ w3,
                               int n4) {
    int i = blockIdx.x * blockDim.x + threadIdx.x;
    if (i >= n4) return;
    const float* src;
    __half* dst;
    switch (blockIdx.y) {
        case 0: src = w0; dst = g_wqhi; break;
        case 1: src = w1; dst = g_wkhi; break;
        case 2: src = w2; dst = g_wvhi; break;
        default: src = w3; dst = g_wohi; break;
    }
    float4 v = ((const float4*)src)[i];
    ((ushort4*)dst)[i] = make_ushort4(h16u(v.x), h16u(v.y), h16u(v.z), h16u(v.w));
}

// ---------------------------------------------------------------------------
// fp16 GEMM mainloop (templated pass count): acc = A @ B^T, 128x128 tile, K=1024.
// NP=2: A corrected (hi+lo); NP=1: A hi only.
// ---------------------------------------------------------------------------
#define BK     32
#define PAD    40
#define TILE_B (128 * PAD * 2)          // 10240 B

template<int NP>
__device__ __forceinline__ void load_stageT(uint32_t sb, int stg, int kc,
        const __half* __restrict__ Ahi, const __half* __restrict__ Alo,
        const __half* __restrict__ Bhi,
        int m0, int n0, int tid) {
    const int NT = NP + 1;
    const __half* srcs[3] = {Ahi, (NP == 2) ? Alo : Bhi, Bhi};
    const int r0s[3] = {m0, (NP == 2) ? m0 : n0, n0};
    uint32_t base = sb + stg * (NT * TILE_B);
#pragma unroll
    for (int t = 0; t < NT; t++) {
        const __half* src = srcs[t];
        const int r0 = r0s[t];
        uint32_t tb = base + t * TILE_B;
#pragma unroll
        for (int it = 0; it < 2; it++) {
            int seg = it * 256 + tid;
            int r = seg >> 2, c8 = (seg & 3) * 8;
            cp16(tb + (r * PAD + c8) * 2,
                 src + (size_t)(r0 + r) * 1024 + kc * BK + c8);
        }
    }
}

template<int NP>
__device__ __forceinline__ void tc_gemm_mainloopT(
        const __half* __restrict__ Ahi, const __half* __restrict__ Alo,
        const __half* __restrict__ Bhi,
        int m0, int n0, float acc[4][4][4]) {
    extern __shared__ char smem[];
    const uint32_t sb = smem_to_u32(smem);
    const int tid = threadIdx.x, lane = tid & 31, warp = tid >> 5;
    const int wm = warp >> 2, wn = warp & 3;
    const int NT = NP + 1;

#pragma unroll
    for (int i = 0; i < 4; i++)
#pragma unroll
        for (int j = 0; j < 4; j++)
#pragma unroll
            for (int e = 0; e < 4; e++) acc[i][j][e] = 0.f;

    load_stageT<NP>(sb, 0, 0, Ahi, Alo, Bhi, m0, n0, tid);
    CP_COMMIT();
    load_stageT<NP>(sb, 1, 1, Ahi, Alo, Bhi, m0, n0, tid);
    CP_COMMIT();

    const int a_row = lane & 15;
    const int a_coff = (lane >> 4) * 8;
    const int b_row = (lane & 7) + ((lane >> 4) << 3);
    const int b_coff = ((lane >> 3) & 1) * 8;

    for (int kc = 0; kc < 1024 / BK; kc++) {
        CP_WAIT1();
        __syncthreads();
        const int stg = kc & 1;
        const uint32_t aHiB = sb + stg * (NT * TILE_B);
        const uint32_t aLoB = aHiB + TILE_B;                 // valid when NP==2
        const uint32_t bHiB = aHiB + (NT - 1) * TILE_B;

#pragma unroll
        for (int ks = 0; ks < 2; ks++) {
            const int k0 = ks * 16;
            uint32_t ahi[4][4], alo[4][4];
#pragma unroll
            for (int mt = 0; mt < 4; mt++) {
                uint32_t off = (uint32_t)(((wm * 64 + mt * 16 + a_row) * PAD + k0 + a_coff) * 2);
                ldmx4(ahi[mt], aHiB + off);
                if (NP == 2) ldmx4(alo[mt], aLoB + off);
            }
            uint32_t bhi[2][4];
#pragma unroll
            for (int nt2 = 0; nt2 < 2; nt2++) {
                uint32_t off = (uint32_t)(((wn * 32 + nt2 * 16 + b_row) * PAD + k0 + b_coff) * 2);
                ldmx4(bhi[nt2], bHiB + off);
            }
#pragma unroll
            for (int mt = 0; mt < 4; mt++)
#pragma unroll
                for (int nt = 0; nt < 4; nt++) {
                    const uint32_t* bh = &bhi[nt >> 1][(nt & 1) * 2];
                    mma16816(acc[mt][nt], ahi[mt], bh);
                    if (NP == 2) mma16816(acc[mt][nt], alo[mt], bh);
                }
        }
        __syncthreads();
        if (kc + 2 < 1024 / BK)
            load_stageT<NP>(sb, stg, kc + 2, Ahi, Alo, Bhi, m0, n0, tid);
        CP_COMMIT();
    }
}

#define QKV_SMEM (2 * 3 * TILE_B)   // 61440
#define OUT_SMEM (2 * 2 * TILE_B)   // 40960

// ---------------------------------------------------------------------------
// QKV GEMM with fused RoPE + fp16 split epilogue.
// ---------------------------------------------------------------------------
__global__ void __launch_bounds__(256, 2) tc_gemm_qkv(
        const int* __restrict__ tok, const int* __restrict__ use_rope,
        const float* __restrict__ cs, const float* __restrict__ sn) {
    const int z = blockIdx.z;
    const __half* bhi = (z == 0) ? g_wqhi : (z == 1) ? g_wkhi : g_wvhi;
    const int m0 = blockIdx.y * 128, n0 = blockIdx.x * 128;

    float acc[4][4][4];
    tc_gemm_mainloopT<2>(g_xhi, g_xlo, bhi, m0, n0, acc);

    const int lane = threadIdx.x & 31, warp = threadIdx.x >> 5;
    const int wm = warp >> 2, wn = warp & 3;
    const int erow = lane >> 2, ecol = (lane & 3) * 2;
    const int ur = (z < 2) ? use_rope[0] : 0;

    unsigned short* dhi = (z == 0) ? (unsigned short*)g_qhi :
                          (z == 1) ? (unsigned short*)g_khi : (unsigned short*)g_vhi;
    unsigned short* dlo = (unsigned short*)g_qlo;

#pragma unroll
    for (int mt = 0; mt < 4; mt++)
#pragma unroll
        for (int nt = 0; nt < 4; nt++) {
            const int c0 = n0 + wn * 32 + nt * 8 + ecol;   // even
            const int j = (c0 & 63) >> 1;
#pragma unroll
            for (int hf = 0; hf < 2; hf++) {
                const int r = m0 + wm * 64 + mt * 16 + erow + hf * 8;
                float v0 = acc[mt][nt][hf * 2];
                float v1 = acc[mt][nt][hf * 2 + 1];
                float rx = v0, ry = v1;
                if (ur) {
                    int pos = tok[r & (S_ - 1)];
                    float c  = cs[pos * 32 + j];
                    float si = sn[pos * 32 + j];
                    rx = v0 * c - v1 * si;
                    ry = v1 * c + v0 * si;
                }
                size_t off = (size_t)r * 1024 + c0;
                *(ushort2*)(dhi + off) = make_ushort2(h16u(rx), h16u(ry));
                if (z == 0)
                    *(ushort2*)(dlo + off) =
                        make_ushort2(h16u(rx - h16f(rx)), h16u(ry - h16f(ry)));
            }
        }
}

// ---------------------------------------------------------------------------
// Output GEMM: 1-pass (y hi only), fp32 epilogue to d_out.
// ---------------------------------------------------------------------------
__global__ void __launch_bounds__(256, 2) tc_gemm_out(float* __restrict__ out) {
    const int m0 = blockIdx.y * 128, n0 = blockIdx.x * 128;
    float acc[4][4][4];
    tc_gemm_mainloopT<1>(g_yhi, nullptr, g_wohi, m0, n0, acc);

    const int lane = threadIdx.x & 31, warp = threadIdx.x >> 5;
    const int wm = warp >> 2, wn = warp & 3;
    const int erow = lane >> 2, ecol = (lane & 3) * 2;
#pragma unroll
    for (int mt = 0; mt < 4; mt++)
#pragma unroll
        for (int nt = 0; nt < 4; nt++) {
            size_t r0 = (size_t)(m0 + wm * 64 + mt * 16 + erow);
            int    c0 = n0 + wn * 32 + nt * 8 + ecol;
            *(float2*)(out + r0 * 1024 + c0)       = make_float2(acc[mt][nt][0], acc[mt][nt][1]);
            *(float2*)(out + (r0 + 8) * 1024 + c0) = make_float2(acc[mt][nt][2], acc[mt][nt][3]);
        }
}

// ---------------------------------------------------------------------------
// Flash attention: S 2-pass, PV 1-pass. Br=128, Bc=64, d=64, 8 warps.
// Causal compare only on the two diagonal tiles.
// ---------------------------------------------------------------------------
#define FPAD   72
#define QT_B   (128 * FPAD * 2)
#define KV_OFF (2 * QT_B)
#define KVT_B  (64 * FPAD * 2)
#define FSTG_B (2 * KVT_B)
#define FLASH_SMEM (KV_OFF + 2 * FSTG_B)   // 73728 B

__device__ __forceinline__ void flash_load_kv(uint32_t sb, int stg, int kt,
                                              int b, int h, int tid) {
    uint32_t base = sb + KV_OFF + stg * FSTG_B;
    size_t krow0 = (size_t)(b * S_ + kt * 64);
    const __half* srcs[2] = {g_khi, g_vhi};
#pragma unroll
    for (int t = 0; t < 2; t++) {
#pragma unroll
        for (int it = 0; it < 2; it++) {
            int seg = it * 256 + tid;
            int r = seg >> 3, c8 = (seg & 7) * 8;
            cp16(base + t * KVT_B + (r * FPAD + c8) * 2,
                 srcs[t] + (krow0 + r) * 1024 + h * HD_ + c8);
        }
    }
}

__global__ void __launch_bounds__(256, 2) flash_mma_kernel() {
    extern __shared__ char fsm[];
    const uint32_t sb = smem_to_u32(fsm);
    const int tid = threadIdx.x, lane = tid & 31, warp = tid >> 5;
    const int qt = gridDim.x - 1 - blockIdx.x;   // heavy tiles first
    const int h = blockIdx.y, b = blockIdx.z;
    const int q0 = qt * 128;
    const size_t qrow0 = (size_t)(b * S_ + q0);
    const int nb = 2 * (qt + 1);

    {
        const __half* qs[2] = {g_qhi, g_qlo};
#pragma unroll
        for (int t = 0; t < 2; t++)
#pragma unroll
            for (int it = 0; it < 4; it++) {
                int seg = it * 256 + tid;
                int r = seg >> 3, c8 = (seg & 7) * 8;
                cp16(sb + t * QT_B + (r * FPAD + c8) * 2,
                     qs[t] + (qrow0 + r) * 1024 + h * HD_ + c8);
            }
    }
    CP_COMMIT();
    flash_load_kv(sb, 0, 0, b, h, tid);
    CP_COMMIT();
    flash_load_kv(sb, 1, 1, b, h, tid);
    CP_COMMIT();

    float oacc[8][4];
#pragma unroll
    for (int nt = 0; nt < 8; nt++)
#pragma unroll
        for (int e = 0; e < 4; e++) oacc[nt][e] = 0.f;
    float m_i[2] = {-1e30f, -1e30f}, l_i[2] = {0.f, 0.f};

    const int a_row = lane & 15;
    const int a_coff = (lane >> 4) * 8;
    const int b_row = (lane & 7) + ((lane >> 4) << 3);
    const int b_coff = ((lane >> 3) & 1) * 8;
    const int wm16 = warp * 16;
    const int vt = lane >> 3, vi = lane & 7;

    for (int kt = 0; kt < nb; kt++) {
        CP_WAIT1();
        __syncthreads();
        const uint32_t kb = sb + KV_OFF + (kt & 1) * FSTG_B;

        // ---- S = Q @ K^T (2-pass) ----
        float sacc[8][4];
#pragma unroll
        for (int nt = 0; nt < 8; nt++)
#pragma unroll
            for (int e = 0; e < 4; e++) sacc[nt][e] = 0.f;

#pragma unroll
        for (int ks = 0; ks < 4; ks++) {
            const int k0 = ks * 16;
            uint32_t aqh[4], aql[4];
            uint32_t qoff = (uint32_t)(((wm16 + a_row) * FPAD + k0 + a_coff) * 2);
            ldmx4(aqh, sb + qoff);
            ldmx4(aql, sb + QT_B + qoff);
            uint32_t bkh[4][4];
#pragma unroll
            for (int nt2 = 0; nt2 < 4; nt2++) {
                uint32_t off = (uint32_t)(((nt2 * 16 + b_row) * FPAD + k0 + b_coff) * 2);
                ldmx4(bkh[nt2], kb + off);
            }
#pragma unroll
            for (int nt = 0; nt < 8; nt++) {
                const uint32_t* bh = &bkh[nt >> 1][(nt & 1) * 2];
                mma16816(sacc[nt], aqh, bh);
                mma16816(sacc[nt], aql, bh);
            }
        }

        // ---- scale + (diagonal-only) causal mask + row max ----
        const bool need_mask = (kt >= nb - 2);
        const int rbase = q0 + wm16 + (lane >> 2);
        const int cbase = kt * 64 + 2 * (lane & 3);
        float mt[2] = {-1e30f, -1e30f};
        if (need_mask) {
#pragma unroll
            for (int nt = 0; nt < 8; nt++)
#pragma unroll
                for (int e = 0; e < 4; e++) {
                    int col = cbase + nt * 8 + (e & 1);
                    int row = rbase + ((e >> 1) << 3);
                    float sv = sacc[nt][e] * 0.125f;
                    if (col > row) sv = -1e30f;
                    sacc[nt][e] = sv;
                    mt[e >> 1] = fmaxf(mt[e >> 1], sv);
                }
        } else {
#pragma unroll
            for (int nt = 0; nt < 8; nt++)
#pragma unroll
                for (int e = 0; e < 4; e++) {
                    float sv = sacc[nt][e] * 0.125f;
                    sacc[nt][e] = sv;
                    mt[e >> 1] = fmaxf(mt[e >> 1], sv);
                }
        }
#pragma unroll
        for (int off = 1; off <= 2; off <<= 1)
#pragma unroll
            for (int rh = 0; rh < 2; rh++)
                mt[rh] = fmaxf(mt[rh], __shfl_xor_sync(0xffffffffu, mt[rh], off));

        float mn[2], alpha[2];
#pragma unroll
        for (int rh = 0; rh < 2; rh++) {
            mn[rh] = fmaxf(m_i[rh], mt[rh]);
            alpha[rh] = __expf(m_i[rh] - mn[rh]);
            m_i[rh] = mn[rh];
        }

        // ---- exp in place + partial sums ----
        float psum[2] = {0.f, 0.f};
#pragma unroll
        for (int nt = 0; nt < 8; nt++)
#pragma unroll
            for (int hf = 0; hf < 2; hf++) {
                float p0 = __expf(sacc[nt][hf * 2]     - mn[hf]);
                float p1 = __expf(sacc[nt][hf * 2 + 1] - mn[hf]);
                psum[hf] += p0 + p1;
                sacc[nt][hf * 2]     = p0;
                sacc[nt][hf * 2 + 1] = p1;
            }
#pragma unroll
        for (int off = 1; off <= 2; off <<= 1)
#pragma unroll
            for (int rh = 0; rh < 2; rh++)
                psum[rh] += __shfl_xor_sync(0xffffffffu, psum[rh], off);
#pragma unroll
        for (int rh = 0; rh < 2; rh++)
            l_i[rh] = l_i[rh] * alpha[rh] + psum[rh];

#pragma unroll
        for (int nt = 0; nt < 8; nt++) {
            oacc[nt][0] *= alpha[0]; oacc[nt][1] *= alpha[0];
            oacc[nt][2] *= alpha[1]; oacc[nt][3] *= alpha[1];
        }

        // ---- O += P @ V (1-pass: P hi only) ----
#pragma unroll
        for (int ks = 0; ks < 4; ks++) {
            const float* s0 = sacc[2 * ks];
            const float* s1 = sacc[2 * ks + 1];
            uint32_t pah[4];
            pah[0] = pack2(s0[0], s0[1]); pah[1] = pack2(s0[2], s0[3]);
            pah[2] = pack2(s1[0], s1[1]); pah[3] = pack2(s1[2], s1[3]);
#pragma unroll
            for (int ntp = 0; ntp < 4; ntp++) {
                uint32_t vaddr = kb + KVT_B +
                    (uint32_t)(((ks * 16 + (vt & 1) * 8 + vi) * FPAD + ntp * 16 + (vt >> 1) * 8) * 2);
                uint32_t vh[4];
                ldmx4t(vh, vaddr);
                mma16816(oacc[2*ntp],   pah, &vh[0]);
                mma16816(oacc[2*ntp+1], pah, &vh[2]);
            }
        }

        __syncthreads();
        if (kt + 2 < nb)
            flash_load_kv(sb, kt & 1, kt + 2, b, h, tid);
        CP_COMMIT();
    }

    // ---- epilogue: y hi fp16 only ----
    float inv0 = 1.f / l_i[0], inv1 = 1.f / l_i[1];
    size_t row0 = qrow0 + wm16 + (lane >> 2);
    int colb = h * HD_ + 2 * (lane & 3);
    unsigned short* yh = (unsigned short*)g_yhi;
#pragma unroll
    for (int nt = 0; nt < 8; nt++) {
        int col = colb + nt * 8;
        *(ushort2*)(yh + row0 * 1024 + col) =
            make_ushort2(h16u(oacc[nt][0] * inv0), h16u(oacc[nt][1] * inv0));
        *(ushort2*)(yh + (row0 + 8) * 1024 + col) =
            make_ushort2(h16u(oacc[nt][2] * inv1), h16u(oacc[nt][3] * inv1));
    }
}

// ---------------------------------------------------------------------------
extern "C" void kernel_launch(void* const* d_in, const int* in_sizes, int n_in,
                              void* d_out, int out_size) {
    const float* x        = (const float*)d_in[0];
    const int*   tok      = (const int*)  d_in[1];
    const int*   use_rope = (const int*)  d_in[2];
    const float* Wq       = (const float*)d_in[3];
    const float* Wk       = (const float*)d_in[4];
    const float* Wv       = (const float*)d_in[5];
    const float* Wo       = (const float*)d_in[6];
    const float* cs       = (const float*)d_in[7];
    const float* sn       = (const float*)d_in[8];
    float* out = (float*)d_out;

    void *p_xhi, *p_xlo;
    cudaGetSymbolAddress(&p_xhi, g_xhi);
    cudaGetSymbolAddress(&p_xlo, g_xlo);

    cudaFuncSetAttribute(tc_gemm_qkv, cudaFuncAttributeMaxDynamicSharedMemorySize, QKV_SMEM);
    cudaFuncSetAttribute(tc_gemm_out, cudaFuncAttributeMaxDynamicSharedMemorySize, OUT_SMEM);
    cudaFuncSetAttribute(flash_mma_kernel, cudaFuncAttributeMaxDynamicSharedMemorySize, FLASH_SMEM);

    const int nx4 = (B_*S_*D_) / 4;
    const int nw4 = (D_*D_) / 4;

    split2_kernel<<<(nx4 + 255) / 256, 256>>>(x, (__half*)p_xhi, (__half*)p_xlo, nx4);
    split1w_kernel<<<dim3((nw4 + 255) / 256, 4), 256>>>(Wq, Wk, Wv, Wo, nw4);

    tc_gemm_qkv<<<dim3(8, 32, 3), 256, QKV_SMEM>>>(tok, use_rope, cs, sn);

    flash_mma_kernel<<<dim3(S_ / 128, H_, B_), 256, FLASH_SMEM>>>();

    tc_gemm_out<<<dim3(8, 32), 256, OUT_SMEM>>>(out);
}

// round 8
// speedup vs baseline: 5.7136x; 1.2804x over previous
#include <cuda_runtime.h>
#include <cuda_fp16.h>
#include <math_constants.h>
#include <cstdint>

#define B_  2
#define S_  2048
#define D_  1024
#define H_  16
#define HD_ 64

// ---------------------------------------------------------------------------
// Scratch (__device__ globals; allocation-free rule)
// ---------------------------------------------------------------------------
__device__ __align__(16) __half g_xhi[B_*S_*D_];
__device__ __align__(16) __half g_yhi[B_*S_*D_];
__device__ __align__(16) __half g_qhi[B_*S_*D_], g_qlo[B_*S_*D_];
__device__ __align__(16) __half g_khi[B_*S_*D_];
__device__ __align__(16) __half g_vhi[B_*S_*D_];
__device__ __align__(16) __half g_wqhi[D_*D_];
__device__ __align__(16) __half g_wkhi[D_*D_];
__device__ __align__(16) __half g_wvhi[D_*D_];
__device__ __align__(16) __half g_wohi[D_*D_];

// ---------------------------------------------------------------------------
// Low-level helpers (base-target instructions only)
// ---------------------------------------------------------------------------
__device__ __forceinline__ uint32_t smem_to_u32(const void* p) {
    uint32_t a;
    asm("{ .reg .u64 t; cvta.to.shared.u64 t, %1; cvt.u32.u64 %0, t; }" : "=r"(a) : "l"(p));
    return a;
}

__device__ __forceinline__ void cp16(uint32_t saddr, const void* gaddr) {
    asm volatile("cp.async.cg.shared.global [%0], [%1], 16;" :: "r"(saddr), "l"(gaddr));
}
#define CP_COMMIT() asm volatile("cp.async.commit_group;" ::: "memory")
#define CP_WAIT1()  asm volatile("cp.async.wait_group 1;"  ::: "memory")

__device__ __forceinline__ void ldmx4(uint32_t* r, uint32_t addr) {
    asm volatile("ldmatrix.sync.aligned.m8n8.x4.shared.b16 {%0,%1,%2,%3}, [%4];"
        : "=r"(r[0]), "=r"(r[1]), "=r"(r[2]), "=r"(r[3]) : "r"(addr));
}
__device__ __forceinline__ void ldmx4t(uint32_t* r, uint32_t addr) {
    asm volatile("ldmatrix.sync.aligned.m8n8.x4.trans.shared.b16 {%0,%1,%2,%3}, [%4];"
        : "=r"(r[0]), "=r"(r[1]), "=r"(r[2]), "=r"(r[3]) : "r"(addr));
}

__device__ __forceinline__ void mma16816(float* c, const uint32_t* a, const uint32_t* b) {
    asm volatile(
        "mma.sync.aligned.m16n8k16.row.col.f32.f16.f16.f32 "
        "{%0,%1,%2,%3}, {%4,%5,%6,%7}, {%8,%9}, {%0,%1,%2,%3};"
        : "+f"(c[0]), "+f"(c[1]), "+f"(c[2]), "+f"(c[3])
        : "r"(a[0]), "r"(a[1]), "r"(a[2]), "r"(a[3]), "r"(b[0]), "r"(b[1]));
}

__device__ __forceinline__ uint16_t h16u(float f) { return __half_as_ushort(__float2half(f)); }
__device__ __forceinline__ float    h16f(float f) { return __half2float(__float2half(f)); }
__device__ __forceinline__ uint32_t pack2(float a, float b) {
    return (uint32_t)h16u(a) | ((uint32_t)h16u(b) << 16);
}

// 0.125 * log2(e): folds the 1/sqrt(HD) scale into the exp2 argument.
#define L2E8 0.18033688011117292f

// ---------------------------------------------------------------------------
// Splits (all 1-pass now except q, which is split in the QKV epilogue)
// ---------------------------------------------------------------------------
__global__ void split1_kernel(const float* __restrict__ src,
                              __half* __restrict__ hi, int n4) {
    int i = blockIdx.x * blockDim.x + threadIdx.x;
    if (i >= n4) return;
    float4 v = ((const float4*)src)[i];
    ((ushort4*)hi)[i] = make_ushort4(h16u(v.x), h16u(v.y), h16u(v.z), h16u(v.w));
}

__global__ void split1w_kernel(const float* __restrict__ w0, const float* __restrict__ w1,
                               const float* __restrict__ w2, const float* __restrict__ w3,
                               int n4) {
    int i = blockIdx.x * blockDim.x + threadIdx.x;
    if (i >= n4) return;
    const float* src;
    __half* dst;
    switch (blockIdx.y) {
        case 0: src = w0; dst = g_wqhi; break;
        case 1: src = w1; dst = g_wkhi; break;
        case 2: src = w2; dst = g_wvhi; break;
        default: src = w3; dst = g_wohi; break;
    }
    float4 v = ((const float4*)src)[i];
    ((ushort4*)dst)[i] = make_ushort4(h16u(v.x), h16u(v.y), h16u(v.z), h16u(v.w));
}

// ---------------------------------------------------------------------------
// fp16 1-pass GEMM mainloop: acc = A @ B^T, 128x128 tile, K=1024.
// ---------------------------------------------------------------------------
#define BK     32
#define PAD    40
#define TILE_B (128 * PAD * 2)          // 10240 B
#define GEMM_SMEM (2 * 2 * TILE_B)      // 40960 B

__device__ __forceinline__ void load_stage1(uint32_t sb, int stg, int kc,
        const __half* __restrict__ Ahi, const __half* __restrict__ Bhi,
        int m0, int n0, int tid) {
    const __half* srcs[2] = {Ahi, Bhi};
    const int r0s[2] = {m0, n0};
    uint32_t base = sb + stg * (2 * TILE_B);
#pragma unroll
    for (int t = 0; t < 2; t++) {
        const __half* src = srcs[t];
        const int r0 = r0s[t];
        uint32_t tb = base + t * TILE_B;
#pragma unroll
        for (int it = 0; it < 2; it++) {
            int seg = it * 256 + tid;
            int r = seg >> 2, c8 = (seg & 3) * 8;
            cp16(tb + (r * PAD + c8) * 2,
                 src + (size_t)(r0 + r) * 1024 + kc * BK + c8);
        }
    }
}

__device__ __forceinline__ void tc_gemm_mainloop1(
        const __half* __restrict__ Ahi, const __half* __restrict__ Bhi,
        int m0, int n0, float acc[4][4][4]) {
    extern __shared__ char smem[];
    const uint32_t sb = smem_to_u32(smem);
    const int tid = threadIdx.x, lane = tid & 31, warp = tid >> 5;
    const int wm = warp >> 2, wn = warp & 3;

#pragma unroll
    for (int i = 0; i < 4; i++)
#pragma unroll
        for (int j = 0; j < 4; j++)
#pragma unroll
            for (int e = 0; e < 4; e++) acc[i][j][e] = 0.f;

    load_stage1(sb, 0, 0, Ahi, Bhi, m0, n0, tid);
    CP_COMMIT();
    load_stage1(sb, 1, 1, Ahi, Bhi, m0, n0, tid);
    CP_COMMIT();

    const int a_row = lane & 15;
    const int a_coff = (lane >> 4) * 8;
    const int b_row = (lane & 7) + ((lane >> 4) << 3);
    const int b_coff = ((lane >> 3) & 1) * 8;

    for (int kc = 0; kc < 1024 / BK; kc++) {
        CP_WAIT1();
        __syncthreads();
        const int stg = kc & 1;
        const uint32_t aHiB = sb + stg * (2 * TILE_B);
        const uint32_t bHiB = aHiB + TILE_B;

#pragma unroll
        for (int ks = 0; ks < 2; ks++) {
            const int k0 = ks * 16;
            uint32_t ahi[4][4];
#pragma unroll
            for (int mt = 0; mt < 4; mt++) {
                uint32_t off = (uint32_t)(((wm * 64 + mt * 16 + a_row) * PAD + k0 + a_coff) * 2);
                ldmx4(ahi[mt], aHiB + off);
            }
            uint32_t bhi[2][4];
#pragma unroll
            for (int nt2 = 0; nt2 < 2; nt2++) {
                uint32_t off = (uint32_t)(((wn * 32 + nt2 * 16 + b_row) * PAD + k0 + b_coff) * 2);
                ldmx4(bhi[nt2], bHiB + off);
            }
#pragma unroll
            for (int mt = 0; mt < 4; mt++)
#pragma unroll
                for (int nt = 0; nt < 4; nt++)
                    mma16816(acc[mt][nt], ahi[mt], &bhi[nt >> 1][(nt & 1) * 2]);
        }
        __syncthreads();
        if (kc + 2 < 1024 / BK)
            load_stage1(sb, stg, kc + 2, Ahi, Bhi, m0, n0, tid);
        CP_COMMIT();
    }
}

// ---------------------------------------------------------------------------
// QKV GEMM (1-pass) with fused RoPE + fp16 split epilogue.
// z=0: Q -> rope -> (qhi, qlo); z=1: K -> rope -> khi; z=2: V -> vhi.
// ---------------------------------------------------------------------------
__global__ void __launch_bounds__(256, 2) tc_gemm_qkv(
        const int* __restrict__ tok, const int* __restrict__ use_rope,
        const float* __restrict__ cs, const float* __restrict__ sn) {
    const int z = blockIdx.z;
    const __half* bhi = (z == 0) ? g_wqhi : (z == 1) ? g_wkhi : g_wvhi;
    const int m0 = blockIdx.y * 128, n0 = blockIdx.x * 128;

    float acc[4][4][4];
    tc_gemm_mainloop1(g_xhi, bhi, m0, n0, acc);

    const int lane = threadIdx.x & 31, warp = threadIdx.x >> 5;
    const int wm = warp >> 2, wn = warp & 3;
    const int erow = lane >> 2, ecol = (lane & 3) * 2;
    const int ur = (z < 2) ? use_rope[0] : 0;

    unsigned short* dhi = (z == 0) ? (unsigned short*)g_qhi :
                          (z == 1) ? (unsigned short*)g_khi : (unsigned short*)g_vhi;
    unsigned short* dlo = (unsigned short*)g_qlo;

#pragma unroll
    for (int mt = 0; mt < 4; mt++)
#pragma unroll
        for (int nt = 0; nt < 4; nt++) {
            const int c0 = n0 + wn * 32 + nt * 8 + ecol;   // even
            const int j = (c0 & 63) >> 1;
#pragma unroll
            for (int hf = 0; hf < 2; hf++) {
                const int r = m0 + wm * 64 + mt * 16 + erow + hf * 8;
                float v0 = acc[mt][nt][hf * 2];
                float v1 = acc[mt][nt][hf * 2 + 1];
                float rx = v0, ry = v1;
                if (ur) {
                    int pos = tok[r & (S_ - 1)];
                    float c  = cs[pos * 32 + j];
                    float si = sn[pos * 32 + j];
                    rx = v0 * c - v1 * si;
                    ry = v1 * c + v0 * si;
                }
                size_t off = (size_t)r * 1024 + c0;
                *(ushort2*)(dhi + off) = make_ushort2(h16u(rx), h16u(ry));
                if (z == 0)
                    *(ushort2*)(dlo + off) =
                        make_ushort2(h16u(rx - h16f(rx)), h16u(ry - h16f(ry)));
            }
        }
}

// ---------------------------------------------------------------------------
// Output GEMM: 1-pass, fp32 epilogue to d_out.
// ---------------------------------------------------------------------------
__global__ void __launch_bounds__(256, 2) tc_gemm_out(float* __restrict__ out) {
    const int m0 = blockIdx.y * 128, n0 = blockIdx.x * 128;
    float acc[4][4][4];
    tc_gemm_mainloop1(g_yhi, g_wohi, m0, n0, acc);

    const int lane = threadIdx.x & 31, warp = threadIdx.x >> 5;
    const int wm = warp >> 2, wn = warp & 3;
    const int erow = lane >> 2, ecol = (lane & 3) * 2;
#pragma unroll
    for (int mt = 0; mt < 4; mt++)
#pragma unroll
        for (int nt = 0; nt < 4; nt++) {
            size_t r0 = (size_t)(m0 + wm * 64 + mt * 16 + erow);
            int    c0 = n0 + wn * 32 + nt * 8 + ecol;
            *(float2*)(out + r0 * 1024 + c0)       = make_float2(acc[mt][nt][0], acc[mt][nt][1]);
            *(float2*)(out + (r0 + 8) * 1024 + c0) = make_float2(acc[mt][nt][2], acc[mt][nt][3]);
        }
}

// ---------------------------------------------------------------------------
// Flash attention: S 2-pass (q corrected), PV 1-pass. exp2-folded softmax.
// Br=128, Bc=64, d=64, 8 warps. Causal compare only on diagonal tiles.
// ---------------------------------------------------------------------------
#define FPAD   72
#define QT_B   (128 * FPAD * 2)
#define KV_OFF (2 * QT_B)
#define KVT_B  (64 * FPAD * 2)
#define FSTG_B (2 * KVT_B)
#define FLASH_SMEM (KV_OFF + 2 * FSTG_B)   // 73728 B

__device__ __forceinline__ void flash_load_kv(uint32_t sb, int stg, int kt,
                                              int b, int h, int tid) {
    uint32_t base = sb + KV_OFF + stg * FSTG_B;
    size_t krow0 = (size_t)(b * S_ + kt * 64);
    const __half* srcs[2] = {g_khi, g_vhi};
#pragma unroll
    for (int t = 0; t < 2; t++) {
#pragma unroll
        for (int it = 0; it < 2; it++) {
            int seg = it * 256 + tid;
            int r = seg >> 3, c8 = (seg & 7) * 8;
            cp16(base + t * KVT_B + (r * FPAD + c8) * 2,
                 srcs[t] + (krow0 + r) * 1024 + h * HD_ + c8);
        }
    }
}

__global__ void __launch_bounds__(256, 2) flash_mma_kernel() {
    extern __shared__ char fsm[];
    const uint32_t sb = smem_to_u32(fsm);
    const int tid = threadIdx.x, lane = tid & 31, warp = tid >> 5;
    const int qt = gridDim.x - 1 - blockIdx.x;   // heavy tiles first
    const int h = blockIdx.y, b = blockIdx.z;
    const int q0 = qt * 128;
    const size_t qrow0 = (size_t)(b * S_ + q0);
    const int nb = 2 * (qt + 1);

    {
        const __half* qs[2] = {g_qhi, g_qlo};
#pragma unroll
        for (int t = 0; t < 2; t++)
#pragma unroll
            for (int it = 0; it < 4; it++) {
                int seg = it * 256 + tid;
                int r = seg >> 3, c8 = (seg & 7) * 8;
                cp16(sb + t * QT_B + (r * FPAD + c8) * 2,
                     qs[t] + (qrow0 + r) * 1024 + h * HD_ + c8);
            }
    }
    CP_COMMIT();
    flash_load_kv(sb, 0, 0, b, h, tid);
    CP_COMMIT();
    flash_load_kv(sb, 1, 1, b, h, tid);
    CP_COMMIT();

    float oacc[8][4];
#pragma unroll
    for (int nt = 0; nt < 8; nt++)
#pragma unroll
        for (int e = 0; e < 4; e++) oacc[nt][e] = 0.f;
    float m_i[2] = {-1e30f, -1e30f}, l_i[2] = {0.f, 0.f};   // m_i in RAW score units

    const int a_row = lane & 15;
    const int a_coff = (lane >> 4) * 8;
    const int b_row = (lane & 7) + ((lane >> 4) << 3);
    const int b_coff = ((lane >> 3) & 1) * 8;
    const int wm16 = warp * 16;
    const int vt = lane >> 3, vi = lane & 7;

    for (int kt = 0; kt < nb; kt++) {
        CP_WAIT1();
        __syncthreads();
        const uint32_t kb = sb + KV_OFF + (kt & 1) * FSTG_B;

        // ---- S = Q @ K^T (2-pass; raw scores, no scale) ----
        float sacc[8][4];
#pragma unroll
        for (int nt = 0; nt < 8; nt++)
#pragma unroll
            for (int e = 0; e < 4; e++) sacc[nt][e] = 0.f;

#pragma unroll
        for (int ks = 0; ks < 4; ks++) {
            const int k0 = ks * 16;
            uint32_t aqh[4], aql[4];
            uint32_t qoff = (uint32_t)(((wm16 + a_row) * FPAD + k0 + a_coff) * 2);
            ldmx4(aqh, sb + qoff);
            ldmx4(aql, sb + QT_B + qoff);
            uint32_t bkh[4][4];
#pragma unroll
            for (int nt2 = 0; nt2 < 4; nt2++) {
                uint32_t off = (uint32_t)(((nt2 * 16 + b_row) * FPAD + k0 + b_coff) * 2);
                ldmx4(bkh[nt2], kb + off);
            }
#pragma unroll
            for (int nt = 0; nt < 8; nt++) {
                const uint32_t* bh = &bkh[nt >> 1][(nt & 1) * 2];
                mma16816(sacc[nt], aqh, bh);
                mma16816(sacc[nt], aql, bh);
            }
        }

        // ---- (diagonal-only) causal mask + raw row max ----
        const bool need_mask = (kt >= nb - 2);
        const int rbase = q0 + wm16 + (lane >> 2);
        const int cbase = kt * 64 + 2 * (lane & 3);
        float mt[2] = {-1e30f, -1e30f};
        if (need_mask) {
#pragma unroll
            for (int nt = 0; nt < 8; nt++)
#pragma unroll
                for (int e = 0; e < 4; e++) {
                    int col = cbase + nt * 8 + (e & 1);
                    int row = rbase + ((e >> 1) << 3);
                    float sv = sacc[nt][e];
                    if (col > row) sv = -1e30f;
                    sacc[nt][e] = sv;
                    mt[e >> 1] = fmaxf(mt[e >> 1], sv);
                }
        } else {
#pragma unroll
            for (int nt = 0; nt < 8; nt++)
#pragma unroll
                for (int e = 0; e < 4; e++)
                    mt[e >> 1] = fmaxf(mt[e >> 1], sacc[nt][e]);
        }
#pragma unroll
        for (int off = 1; off <= 2; off <<= 1)
#pragma unroll
            for (int rh = 0; rh < 2; rh++)
                mt[rh] = fmaxf(mt[rh], __shfl_xor_sync(0xffffffffu, mt[rh], off));

        float mn[2], alpha[2], mnl[2];
#pragma unroll
        for (int rh = 0; rh < 2; rh++) {
            mn[rh] = fmaxf(m_i[rh], mt[rh]);
            alpha[rh] = exp2f((m_i[rh] - mn[rh]) * L2E8);
            m_i[rh] = mn[rh];
            mnl[rh] = mn[rh] * L2E8;
        }

        // ---- exp2(FMA) in place + partial sums ----
        float psum[2] = {0.f, 0.f};
#pragma unroll
        for (int nt = 0; nt < 8; nt++)
#pragma unroll
            for (int hf = 0; hf < 2; hf++) {
                float p0 = exp2f(fmaf(sacc[nt][hf * 2],     L2E8, -mnl[hf]));
                float p1 = exp2f(fmaf(sacc[nt][hf * 2 + 1], L2E8, -mnl[hf]));
                psum[hf] += p0 + p1;
                sacc[nt][hf * 2]     = p0;
                sacc[nt][hf * 2 + 1] = p1;
            }
#pragma unroll
        for (int off = 1; off <= 2; off <<= 1)
#pragma unroll
            for (int rh = 0; rh < 2; rh++)
                psum[rh] += __shfl_xor_sync(0xffffffffu, psum[rh], off);
#pragma unroll
        for (int rh = 0; rh < 2; rh++)
            l_i[rh] = l_i[rh] * alpha[rh] + psum[rh];

#pragma unroll
        for (int nt = 0; nt < 8; nt++) {
            oacc[nt][0] *= alpha[0]; oacc[nt][1] *= alpha[0];
            oacc[nt][2] *= alpha[1]; oacc[nt][3] *= alpha[1];
        }

        // ---- O += P @ V (1-pass) ----
#pragma unroll
        for (int ks = 0; ks < 4; ks++) {
            const float* s0 = sacc[2 * ks];
            const float* s1 = sacc[2 * ks + 1];
            uint32_t pah[4];
            pah[0] = pack2(s0[0], s0[1]); pah[1] = pack2(s0[2], s0[3]);
            pah[2] = pack2(s1[0], s1[1]); pah[3] = pack2(s1[2], s1[3]);
#pragma unroll
            for (int ntp = 0; ntp < 4; ntp++) {
                uint32_t vaddr = kb + KVT_B +
                    (uint32_t)(((ks * 16 + (vt & 1) * 8 + vi) * FPAD + ntp * 16 + (vt >> 1) * 8) * 2);
                uint32_t vh[4];
                ldmx4t(vh, vaddr);
                mma16816(oacc[2*ntp],   pah, &vh[0]);
                mma16816(oacc[2*ntp+1], pah, &vh[2]);
            }
        }

        __syncthreads();
        if (kt + 2 < nb)
            flash_load_kv(sb, kt & 1, kt + 2, b, h, tid);
        CP_COMMIT();
    }

    // ---- epilogue: y hi fp16 ----
    float inv0 = 1.f / l_i[0], inv1 = 1.f / l_i[1];
    size_t row0 = qrow0 + wm16 + (lane >> 2);
    int colb = h * HD_ + 2 * (lane & 3);
    unsigned short* yh = (unsigned short*)g_yhi;
#pragma unroll
    for (int nt = 0; nt < 8; nt++) {
        int col = colb + nt * 8;
        *(ushort2*)(yh + row0 * 1024 + col) =
            make_ushort2(h16u(oacc[nt][0] * inv0), h16u(oacc[nt][1] * inv0));
        *(ushort2*)(yh + (row0 + 8) * 1024 + col) =
            make_ushort2(h16u(oacc[nt][2] * inv1), h16u(oacc[nt][3] * inv1));
    }
}

// ---------------------------------------------------------------------------
extern "C" void kernel_launch(void* const* d_in, const int* in_sizes, int n_in,
                              void* d_out, int out_size) {
    const float* x        = (const float*)d_in[0];
    const int*   tok      = (const int*)  d_in[1];
    const int*   use_rope = (const int*)  d_in[2];
    const float* Wq       = (const float*)d_in[3];
    const float* Wk       = (const float*)d_in[4];
    const float* Wv       = (const float*)d_in[5];
    const float* Wo       = (const float*)d_in[6];
    const float* cs       = (const float*)d_in[7];
    const float* sn       = (const float*)d_in[8];
    float* out = (float*)d_out;

    void *p_xhi;
    cudaGetSymbolAddress(&p_xhi, g_xhi);

    cudaFuncSetAttribute(tc_gemm_qkv, cudaFuncAttributeMaxDynamicSharedMemorySize, GEMM_SMEM);
    cudaFuncSetAttribute(tc_gemm_out, cudaFuncAttributeMaxDynamicSharedMemorySize, GEMM_SMEM);
    cudaFuncSetAttribute(flash_mma_kernel, cudaFuncAttributeMaxDynamicSharedMemorySize, FLASH_SMEM);

    const int nx4 = (B_*S_*D_) / 4;
    const int nw4 = (D_*D_) / 4;

    split1_kernel<<<(nx4 + 255) / 256, 256>>>(x, (__half*)p_xhi, nx4);
    split1w_kernel<<<dim3((nw4 + 255) / 256, 4), 256>>>(Wq, Wk, Wv, Wo, nw4);

    tc_gemm_qkv<<<dim3(8, 32, 3), 256, GEMM_SMEM>>>(tok, use_rope, cs, sn);

    flash_mma_kernel<<<dim3(S_ / 128, H_, B_), 256, FLASH_SMEM>>>();

    tc_gemm_out<<<dim3(8, 32), 256, GEMM_SMEM>>>(out);
}

// round 9
// speedup vs baseline: 6.3273x; 1.1074x over previous
#include <cuda_runtime.h>
#include <cuda_fp16.h>
#include <math_constants.h>
#include <cstdint>

#define B_  2
#define S_  2048
#define D_  1024
#define H_  16
#define HD_ 64

// ---------------------------------------------------------------------------
// Scratch (__device__ globals; allocation-free rule)
// ---------------------------------------------------------------------------
__device__ __align__(16) __half g_xhi[B_*S_*D_];
__device__ __align__(16) __half g_yhi[B_*S_*D_];
__device__ __align__(16) __half g_qhi[B_*S_*D_];
__device__ __align__(16) __half g_khi[B_*S_*D_];
__device__ __align__(16) __half g_vhi[B_*S_*D_];
__device__ __align__(16) __half g_wqhi[D_*D_];
__device__ __align__(16) __half g_wkhi[D_*D_];
__device__ __align__(16) __half g_wvhi[D_*D_];
__device__ __align__(16) __half g_wohi[D_*D_];

// ---------------------------------------------------------------------------
// Low-level helpers (base-target instructions only)
// ---------------------------------------------------------------------------
__device__ __forceinline__ uint32_t smem_to_u32(const void* p) {
    uint32_t a;
    asm("{ .reg .u64 t; cvta.to.shared.u64 t, %1; cvt.u32.u64 %0, t; }" : "=r"(a) : "l"(p));
    return a;
}

__device__ __forceinline__ void cp16(uint32_t saddr, const void* gaddr) {
    asm volatile("cp.async.cg.shared.global [%0], [%1], 16;" :: "r"(saddr), "l"(gaddr));
}
#define CP_COMMIT() asm volatile("cp.async.commit_group;" ::: "memory")
#define CP_WAIT1()  asm volatile("cp.async.wait_group 1;"  ::: "memory")

__device__ __forceinline__ void ldmx4(uint32_t* r, uint32_t addr) {
    asm volatile("ldmatrix.sync.aligned.m8n8.x4.shared.b16 {%0,%1,%2,%3}, [%4];"
        : "=r"(r[0]), "=r"(r[1]), "=r"(r[2]), "=r"(r[3]) : "r"(addr));
}
__device__ __forceinline__ void ldmx4t(uint32_t* r, uint32_t addr) {
    asm volatile("ldmatrix.sync.aligned.m8n8.x4.trans.shared.b16 {%0,%1,%2,%3}, [%4];"
        : "=r"(r[0]), "=r"(r[1]), "=r"(r[2]), "=r"(r[3]) : "r"(addr));
}

__device__ __forceinline__ void mma16816(float* c, const uint32_t* a, const uint32_t* b) {
    asm volatile(
        "mma.sync.aligned.m16n8k16.row.col.f32.f16.f16.f32 "
        "{%0,%1,%2,%3}, {%4,%5,%6,%7}, {%8,%9}, {%0,%1,%2,%3};"
        : "+f"(c[0]), "+f"(c[1]), "+f"(c[2]), "+f"(c[3])
        : "r"(a[0]), "r"(a[1]), "r"(a[2]), "r"(a[3]), "r"(b[0]), "r"(b[1]));
}

__device__ __forceinline__ uint16_t h16u(float f) { return __half_as_ushort(__float2half(f)); }
__device__ __forceinline__ uint32_t pack2(float a, float b) {
    return (uint32_t)h16u(a) | ((uint32_t)h16u(b) << 16);
}

// 0.125 * log2(e): folds the 1/sqrt(HD) scale into the exp2 argument.
#define L2E8 0.18033688011117292f

// ---------------------------------------------------------------------------
// Splits (all 1-pass)
// ---------------------------------------------------------------------------
__global__ void split1_kernel(const float* __restrict__ src,
                              __half* __restrict__ hi, int n4) {
    int i = blockIdx.x * blockDim.x + threadIdx.x;
    if (i >= n4) return;
    float4 v = ((const float4*)src)[i];
    ((ushort4*)hi)[i] = make_ushort4(h16u(v.x), h16u(v.y), h16u(v.z), h16u(v.w));
}

__global__ void split1w_kernel(const float* __restrict__ w0, const float* __restrict__ w1,
                               const float* __restrict__ w2, const float* __restrict__ w3,
                               int n4) {
    int i = blockIdx.x * blockDim.x + threadIdx.x;
    if (i >= n4) return;
    const float* src;
    __half* dst;
    switch (blockIdx.y) {
        case 0: src = w0; dst = g_wqhi; break;
        case 1: src = w1; dst = g_wkhi; break;
        case 2: src = w2; dst = g_wvhi; break;
        default: src = w3; dst = g_wohi; break;
    }
    float4 v = ((const float4*)src)[i];
    ((ushort4*)dst)[i] = make_ushort4(h16u(v.x), h16u(v.y), h16u(v.z), h16u(v.w));
}

// ---------------------------------------------------------------------------
// fp16 1-pass GEMM mainloop: acc = A @ B^T, 128x128 tile, K=1024.
// ---------------------------------------------------------------------------
#define BK     32
#define PAD    40
#define TILE_B (128 * PAD * 2)          // 10240 B
#define GEMM_SMEM (2 * 2 * TILE_B)      // 40960 B

__device__ __forceinline__ void load_stage1(uint32_t sb, int stg, int kc,
        const __half* __restrict__ Ahi, const __half* __restrict__ Bhi,
        int m0, int n0, int tid) {
    const __half* srcs[2] = {Ahi, Bhi};
    const int r0s[2] = {m0, n0};
    uint32_t base = sb + stg * (2 * TILE_B);
#pragma unroll
    for (int t = 0; t < 2; t++) {
        const __half* src = srcs[t];
        const int r0 = r0s[t];
        uint32_t tb = base + t * TILE_B;
#pragma unroll
        for (int it = 0; it < 2; it++) {
            int seg = it * 256 + tid;
            int r = seg >> 2, c8 = (seg & 3) * 8;
            cp16(tb + (r * PAD + c8) * 2,
                 src + (size_t)(r0 + r) * 1024 + kc * BK + c8);
        }
    }
}

__device__ __forceinline__ void tc_gemm_mainloop1(
        const __half* __restrict__ Ahi, const __half* __restrict__ Bhi,
        int m0, int n0, float acc[4][4][4]) {
    extern __shared__ char smem[];
    const uint32_t sb = smem_to_u32(smem);
    const int tid = threadIdx.x, lane = tid & 31, warp = tid >> 5;
    const int wm = warp >> 2, wn = warp & 3;

#pragma unroll
    for (int i = 0; i < 4; i++)
#pragma unroll
        for (int j = 0; j < 4; j++)
#pragma unroll
            for (int e = 0; e < 4; e++) acc[i][j][e] = 0.f;

    load_stage1(sb, 0, 0, Ahi, Bhi, m0, n0, tid);
    CP_COMMIT();
    load_stage1(sb, 1, 1, Ahi, Bhi, m0, n0, tid);
    CP_COMMIT();

    const int a_row = lane & 15;
    const int a_coff = (lane >> 4) * 8;
    const int b_row = (lane & 7) + ((lane >> 4) << 3);
    const int b_coff = ((lane >> 3) & 1) * 8;

    for (int kc = 0; kc < 1024 / BK; kc++) {
        CP_WAIT1();
        __syncthreads();
        const int stg = kc & 1;
        const uint32_t aHiB = sb + stg * (2 * TILE_B);
        const uint32_t bHiB = aHiB + TILE_B;

#pragma unroll
        for (int ks = 0; ks < 2; ks++) {
            const int k0 = ks * 16;
            uint32_t ahi[4][4];
#pragma unroll
            for (int mt = 0; mt < 4; mt++) {
                uint32_t off = (uint32_t)(((wm * 64 + mt * 16 + a_row) * PAD + k0 + a_coff) * 2);
                ldmx4(ahi[mt], aHiB + off);
            }
            uint32_t bhi[2][4];
#pragma unroll
            for (int nt2 = 0; nt2 < 2; nt2++) {
                uint32_t off = (uint32_t)(((wn * 32 + nt2 * 16 + b_row) * PAD + k0 + b_coff) * 2);
                ldmx4(bhi[nt2], bHiB + off);
            }
#pragma unroll
            for (int mt = 0; mt < 4; mt++)
#pragma unroll
                for (int nt = 0; nt < 4; nt++)
                    mma16816(acc[mt][nt], ahi[mt], &bhi[nt >> 1][(nt & 1) * 2]);
        }
        __syncthreads();
        if (kc + 2 < 1024 / BK)
            load_stage1(sb, stg, kc + 2, Ahi, Bhi, m0, n0, tid);
        CP_COMMIT();
    }
}

// ---------------------------------------------------------------------------
// QKV GEMM (1-pass) with fused RoPE + fp16 epilogue.
// z=0: Q -> rope -> qhi; z=1: K -> rope -> khi; z=2: V -> vhi.
// ---------------------------------------------------------------------------
__global__ void __launch_bounds__(256, 2) tc_gemm_qkv(
        const int* __restrict__ tok, const int* __restrict__ use_rope,
        const float* __restrict__ cs, const float* __restrict__ sn) {
    const int z = blockIdx.z;
    const __half* bhi = (z == 0) ? g_wqhi : (z == 1) ? g_wkhi : g_wvhi;
    const int m0 = blockIdx.y * 128, n0 = blockIdx.x * 128;

    float acc[4][4][4];
    tc_gemm_mainloop1(g_xhi, bhi, m0, n0, acc);

    const int lane = threadIdx.x & 31, warp = threadIdx.x >> 5;
    const int wm = warp >> 2, wn = warp & 3;
    const int erow = lane >> 2, ecol = (lane & 3) * 2;
    const int ur = (z < 2) ? use_rope[0] : 0;

    unsigned short* dhi = (z == 0) ? (unsigned short*)g_qhi :
                          (z == 1) ? (unsigned short*)g_khi : (unsigned short*)g_vhi;

#pragma unroll
    for (int mt = 0; mt < 4; mt++)
#pragma unroll
        for (int nt = 0; nt < 4; nt++) {
            const int c0 = n0 + wn * 32 + nt * 8 + ecol;   // even
            const int j = (c0 & 63) >> 1;
#pragma unroll
            for (int hf = 0; hf < 2; hf++) {
                const int r = m0 + wm * 64 + mt * 16 + erow + hf * 8;
                float v0 = acc[mt][nt][hf * 2];
                float v1 = acc[mt][nt][hf * 2 + 1];
                float rx = v0, ry = v1;
                if (ur) {
                    int pos = tok[r & (S_ - 1)];
                    float c  = cs[pos * 32 + j];
                    float si = sn[pos * 32 + j];
                    rx = v0 * c - v1 * si;
                    ry = v1 * c + v0 * si;
                }
                *(ushort2*)(dhi + (size_t)r * 1024 + c0) = make_ushort2(h16u(rx), h16u(ry));
            }
        }
}

// ---------------------------------------------------------------------------
// Output GEMM: 1-pass, fp32 epilogue to d_out.
// ---------------------------------------------------------------------------
__global__ void __launch_bounds__(256, 2) tc_gemm_out(float* __restrict__ out) {
    const int m0 = blockIdx.y * 128, n0 = blockIdx.x * 128;
    float acc[4][4][4];
    tc_gemm_mainloop1(g_yhi, g_wohi, m0, n0, acc);

    const int lane = threadIdx.x & 31, warp = threadIdx.x >> 5;
    const int wm = warp >> 2, wn = warp & 3;
    const int erow = lane >> 2, ecol = (lane & 3) * 2;
#pragma unroll
    for (int mt = 0; mt < 4; mt++)
#pragma unroll
        for (int nt = 0; nt < 4; nt++) {
            size_t r0 = (size_t)(m0 + wm * 64 + mt * 16 + erow);
            int    c0 = n0 + wn * 32 + nt * 8 + ecol;
            *(float2*)(out + r0 * 1024 + c0)       = make_float2(acc[mt][nt][0], acc[mt][nt][1]);
            *(float2*)(out + (r0 + 8) * 1024 + c0) = make_float2(acc[mt][nt][2], acc[mt][nt][3]);
        }
}

// ---------------------------------------------------------------------------
// Flash attention: fully 1-pass fp16. exp2-folded softmax.
// Br=128, Bc=64, d=64, 8 warps. Causal compare only on diagonal tiles.
// ---------------------------------------------------------------------------
#define FPAD   72
#define QT_B   (128 * FPAD * 2)            // 18432 B (single Q tile now)
#define KV_OFF (QT_B)
#define KVT_B  (64 * FPAD * 2)             // 9216 B
#define FSTG_B (2 * KVT_B)                 // 18432 per stage (khi, vhi)
#define FLASH_SMEM (KV_OFF + 2 * FSTG_B)   // 55296 B

__device__ __forceinline__ void flash_load_kv(uint32_t sb, int stg, int kt,
                                              int b, int h, int tid) {
    uint32_t base = sb + KV_OFF + stg * FSTG_B;
    size_t krow0 = (size_t)(b * S_ + kt * 64);
    const __half* srcs[2] = {g_khi, g_vhi};
#pragma unroll
    for (int t = 0; t < 2; t++) {
#pragma unroll
        for (int it = 0; it < 2; it++) {
            int seg = it * 256 + tid;
            int r = seg >> 3, c8 = (seg & 7) * 8;
            cp16(base + t * KVT_B + (r * FPAD + c8) * 2,
                 srcs[t] + (krow0 + r) * 1024 + h * HD_ + c8);
        }
    }
}

__global__ void __launch_bounds__(256, 2) flash_mma_kernel() {
    extern __shared__ char fsm[];
    const uint32_t sb = smem_to_u32(fsm);
    const int tid = threadIdx.x, lane = tid & 31, warp = tid >> 5;
    const int qt = gridDim.x - 1 - blockIdx.x;   // heavy tiles first
    const int h = blockIdx.y, b = blockIdx.z;
    const int q0 = qt * 128;
    const size_t qrow0 = (size_t)(b * S_ + q0);
    const int nb = 2 * (qt + 1);

    // async-load Q tile (hi only)
#pragma unroll
    for (int it = 0; it < 4; it++) {
        int seg = it * 256 + tid;
        int r = seg >> 3, c8 = (seg & 7) * 8;
        cp16(sb + (r * FPAD + c8) * 2,
             g_qhi + (qrow0 + r) * 1024 + h * HD_ + c8);
    }
    CP_COMMIT();
    flash_load_kv(sb, 0, 0, b, h, tid);
    CP_COMMIT();
    flash_load_kv(sb, 1, 1, b, h, tid);
    CP_COMMIT();

    float oacc[8][4];
#pragma unroll
    for (int nt = 0; nt < 8; nt++)
#pragma unroll
        for (int e = 0; e < 4; e++) oacc[nt][e] = 0.f;
    float m_i[2] = {-1e30f, -1e30f}, l_i[2] = {0.f, 0.f};   // m_i in RAW score units

    const int a_row = lane & 15;
    const int a_coff = (lane >> 4) * 8;
    const int b_row = (lane & 7) + ((lane >> 4) << 3);
    const int b_coff = ((lane >> 3) & 1) * 8;
    const int wm16 = warp * 16;
    const int vt = lane >> 3, vi = lane & 7;

    for (int kt = 0; kt < nb; kt++) {
        CP_WAIT1();
        __syncthreads();
        const uint32_t kb = sb + KV_OFF + (kt & 1) * FSTG_B;

        // ---- S = Q @ K^T (1-pass; raw scores) ----
        float sacc[8][4];
#pragma unroll
        for (int nt = 0; nt < 8; nt++)
#pragma unroll
            for (int e = 0; e < 4; e++) sacc[nt][e] = 0.f;

#pragma unroll
        for (int ks = 0; ks < 4; ks++) {
            const int k0 = ks * 16;
            uint32_t aqh[4];
            ldmx4(aqh, sb + (uint32_t)(((wm16 + a_row) * FPAD + k0 + a_coff) * 2));
            uint32_t bkh[4][4];
#pragma unroll
            for (int nt2 = 0; nt2 < 4; nt2++) {
                uint32_t off = (uint32_t)(((nt2 * 16 + b_row) * FPAD + k0 + b_coff) * 2);
                ldmx4(bkh[nt2], kb + off);
            }
#pragma unroll
            for (int nt = 0; nt < 8; nt++)
                mma16816(sacc[nt], aqh, &bkh[nt >> 1][(nt & 1) * 2]);
        }

        // ---- (diagonal-only) causal mask + raw row max ----
        const bool need_mask = (kt >= nb - 2);
        const int rbase = q0 + wm16 + (lane >> 2);
        const int cbase = kt * 64 + 2 * (lane & 3);
        float mt[2] = {-1e30f, -1e30f};
        if (need_mask) {
#pragma unroll
            for (int nt = 0; nt < 8; nt++)
#pragma unroll
                for (int e = 0; e < 4; e++) {
                    int col = cbase + nt * 8 + (e & 1);
                    int row = rbase + ((e >> 1) << 3);
                    float sv = sacc[nt][e];
                    if (col > row) sv = -1e30f;
                    sacc[nt][e] = sv;
                    mt[e >> 1] = fmaxf(mt[e >> 1], sv);
                }
        } else {
#pragma unroll
            for (int nt = 0; nt < 8; nt++)
#pragma unroll
                for (int e = 0; e < 4; e++)
                    mt[e >> 1] = fmaxf(mt[e >> 1], sacc[nt][e]);
        }
#pragma unroll
        for (int off = 1; off <= 2; off <<= 1)
#pragma unroll
            for (int rh = 0; rh < 2; rh++)
                mt[rh] = fmaxf(mt[rh], __shfl_xor_sync(0xffffffffu, mt[rh], off));

        float mn[2], alpha[2], mnl[2];
#pragma unroll
        for (int rh = 0; rh < 2; rh++) {
            mn[rh] = fmaxf(m_i[rh], mt[rh]);
            alpha[rh] = exp2f((m_i[rh] - mn[rh]) * L2E8);
            m_i[rh] = mn[rh];
            mnl[rh] = mn[rh] * L2E8;
        }

        // ---- exp2(FMA) in place + partial sums ----
        float psum[2] = {0.f, 0.f};
#pragma unroll
        for (int nt = 0; nt < 8; nt++)
#pragma unroll
            for (int hf = 0; hf < 2; hf++) {
                float p0 = exp2f(fmaf(sacc[nt][hf * 2],     L2E8, -mnl[hf]));
                float p1 = exp2f(fmaf(sacc[nt][hf * 2 + 1], L2E8, -mnl[hf]));
                psum[hf] += p0 + p1;
                sacc[nt][hf * 2]     = p0;
                sacc[nt][hf * 2 + 1] = p1;
            }
#pragma unroll
        for (int off = 1; off <= 2; off <<= 1)
#pragma unroll
            for (int rh = 0; rh < 2; rh++)
                psum[rh] += __shfl_xor_sync(0xffffffffu, psum[rh], off);
#pragma unroll
        for (int rh = 0; rh < 2; rh++)
            l_i[rh] = l_i[rh] * alpha[rh] + psum[rh];

#pragma unroll
        for (int nt = 0; nt < 8; nt++) {
            oacc[nt][0] *= alpha[0]; oacc[nt][1] *= alpha[0];
            oacc[nt][2] *= alpha[1]; oacc[nt][3] *= alpha[1];
        }

        // ---- O += P @ V (1-pass) ----
#pragma unroll
        for (int ks = 0; ks < 4; ks++) {
            const float* s0 = sacc[2 * ks];
            const float* s1 = sacc[2 * ks + 1];
            uint32_t pah[4];
            pah[0] = pack2(s0[0], s0[1]); pah[1] = pack2(s0[2], s0[3]);
            pah[2] = pack2(s1[0], s1[1]); pah[3] = pack2(s1[2], s1[3]);
#pragma unroll
            for (int ntp = 0; ntp < 4; ntp++) {
                uint32_t vaddr = kb + KVT_B +
                    (uint32_t)(((ks * 16 + (vt & 1) * 8 + vi) * FPAD + ntp * 16 + (vt >> 1) * 8) * 2);
                uint32_t vh[4];
                ldmx4t(vh, vaddr);
                mma16816(oacc[2*ntp],   pah, &vh[0]);
                mma16816(oacc[2*ntp+1], pah, &vh[2]);
            }
        }

        __syncthreads();
        if (kt + 2 < nb)
            flash_load_kv(sb, kt & 1, kt + 2, b, h, tid);
        CP_COMMIT();
    }

    // ---- epilogue: y hi fp16 ----
    float inv0 = 1.f / l_i[0], inv1 = 1.f / l_i[1];
    size_t row0 = qrow0 + wm16 + (lane >> 2);
    int colb = h * HD_ + 2 * (lane & 3);
    unsigned short* yh = (unsigned short*)g_yhi;
#pragma unroll
    for (int nt = 0; nt < 8; nt++) {
        int col = colb + nt * 8;
        *(ushort2*)(yh + row0 * 1024 + col) =
            make_ushort2(h16u(oacc[nt][0] * inv0), h16u(oacc[nt][1] * inv0));
        *(ushort2*)(yh + (row0 + 8) * 1024 + col) =
            make_ushort2(h16u(oacc[nt][2] * inv1), h16u(oacc[nt][3] * inv1));
    }
}

// ---------------------------------------------------------------------------
extern "C" void kernel_launch(void* const* d_in, const int* in_sizes, int n_in,
                              void* d_out, int out_size) {
    const float* x        = (const float*)d_in[0];
    const int*   tok      = (const int*)  d_in[1];
    const int*   use_rope = (const int*)  d_in[2];
    const float* Wq       = (const float*)d_in[3];
    const float* Wk       = (const float*)d_in[4];
    const float* Wv       = (const float*)d_in[5];
    const float* Wo       = (const float*)d_in[6];
    const float* cs       = (const float*)d_in[7];
    const float* sn       = (const float*)d_in[8];
    float* out = (float*)d_out;

    void *p_xhi;
    cudaGetSymbolAddress(&p_xhi, g_xhi);

    cudaFuncSetAttribute(tc_gemm_qkv, cudaFuncAttributeMaxDynamicSharedMemorySize, GEMM_SMEM);
    cudaFuncSetAttribute(tc_gemm_out, cudaFuncAttributeMaxDynamicSharedMemorySize, GEMM_SMEM);
    cudaFuncSetAttribute(flash_mma_kernel, cudaFuncAttributeMaxDynamicSharedMemorySize, FLASH_SMEM);

    const int nx4 = (B_*S_*D_) / 4;
    const int nw4 = (D_*D_) / 4;

    split1_kernel<<<(nx4 + 255) / 256, 256>>>(x, (__half*)p_xhi, nx4);
    split1w_kernel<<<dim3((nw4 + 255) / 256, 4), 256>>>(Wq, Wk, Wv, Wo, nw4);

    tc_gemm_qkv<<<dim3(8, 32, 3), 256, GEMM_SMEM>>>(tok, use_rope, cs, sn);

    flash_mma_kernel<<<dim3(S_ / 128, H_, B_), 256, FLASH_SMEM>>>();

    tc_gemm_out<<<dim3(8, 32), 256, GEMM_SMEM>>>(out);
}

// round 10
// speedup vs baseline: 6.4961x; 1.0267x over previous
#include <cuda_runtime.h>
#include <cuda_fp16.h>
#include <math_constants.h>
#include <cstdint>

#define B_  2
#define S_  2048
#define D_  1024
#define H_  16
#define HD_ 64

// ---------------------------------------------------------------------------
// Scratch (__device__ globals; allocation-free rule)
// ---------------------------------------------------------------------------
__device__ __align__(16) __half g_xhi[B_*S_*D_];
__device__ __align__(16) __half g_yhi[B_*S_*D_];
__device__ __align__(16) __half g_qhi[B_*S_*D_];
__device__ __align__(16) __half g_khi[B_*S_*D_];
__device__ __align__(16) __half g_vhi[B_*S_*D_];
__device__ __align__(16) __half g_wqhi[D_*D_];
__device__ __align__(16) __half g_wkhi[D_*D_];
__device__ __align__(16) __half g_wvhi[D_*D_];
__device__ __align__(16) __half g_wohi[D_*D_];

// ---------------------------------------------------------------------------
// Low-level helpers (base-target instructions only)
// ---------------------------------------------------------------------------
__device__ __forceinline__ uint32_t smem_to_u32(const void* p) {
    uint32_t a;
    asm("{ .reg .u64 t; cvta.to.shared.u64 t, %1; cvt.u32.u64 %0, t; }" : "=r"(a) : "l"(p));
    return a;
}

__device__ __forceinline__ void cp16(uint32_t saddr, const void* gaddr) {
    asm volatile("cp.async.cg.shared.global [%0], [%1], 16;" :: "r"(saddr), "l"(gaddr));
}
#define CP_COMMIT() asm volatile("cp.async.commit_group;" ::: "memory")
#define CP_WAIT1()  asm volatile("cp.async.wait_group 1;"  ::: "memory")

__device__ __forceinline__ void ldmx4(uint32_t* r, uint32_t addr) {
    asm volatile("ldmatrix.sync.aligned.m8n8.x4.shared.b16 {%0,%1,%2,%3}, [%4];"
        : "=r"(r[0]), "=r"(r[1]), "=r"(r[2]), "=r"(r[3]) : "r"(addr));
}
__device__ __forceinline__ void ldmx4t(uint32_t* r, uint32_t addr) {
    asm volatile("ldmatrix.sync.aligned.m8n8.x4.trans.shared.b16 {%0,%1,%2,%3}, [%4];"
        : "=r"(r[0]), "=r"(r[1]), "=r"(r[2]), "=r"(r[3]) : "r"(addr));
}

__device__ __forceinline__ void mma16816(float* c, const uint32_t* a, const uint32_t* b) {
    asm volatile(
        "mma.sync.aligned.m16n8k16.row.col.f32.f16.f16.f32 "
        "{%0,%1,%2,%3}, {%4,%5,%6,%7}, {%8,%9}, {%0,%1,%2,%3};"
        : "+f"(c[0]), "+f"(c[1]), "+f"(c[2]), "+f"(c[3])
        : "r"(a[0]), "r"(a[1]), "r"(a[2]), "r"(a[3]), "r"(b[0]), "r"(b[1]));
}

__device__ __forceinline__ uint16_t h16u(float f) { return __half_as_ushort(__float2half(f)); }
__device__ __forceinline__ uint32_t pack2(float a, float b) {
    return (uint32_t)h16u(a) | ((uint32_t)h16u(b) << 16);
}

// 0.125 * log2(e)
#define L2E8 0.18033688011117292f

// ---------------------------------------------------------------------------
// Splits
// ---------------------------------------------------------------------------
__global__ void split1_kernel(const float* __restrict__ src,
                              __half* __restrict__ hi, int n4) {
    int i = blockIdx.x * blockDim.x + threadIdx.x;
    if (i >= n4) return;
    float4 v = ((const float4*)src)[i];
    ((ushort4*)hi)[i] = make_ushort4(h16u(v.x), h16u(v.y), h16u(v.z), h16u(v.w));
}

__global__ void split1w_kernel(const float* __restrict__ w0, const float* __restrict__ w1,
                               const float* __restrict__ w2, const float* __restrict__ w3,
                               int n4) {
    int i = blockIdx.x * blockDim.x + threadIdx.x;
    if (i >= n4) return;
    const float* src;
    __half* dst;
    switch (blockIdx.y) {
        case 0: src = w0; dst = g_wqhi; break;
        case 1: src = w1; dst = g_wkhi; break;
        case 2: src = w2; dst = g_wvhi; break;
        default: src = w3; dst = g_wohi; break;
    }
    float4 v = ((const float4*)src)[i];
    ((ushort4*)dst)[i] = make_ushort4(h16u(v.x), h16u(v.y), h16u(v.z), h16u(v.w));
}

// ---------------------------------------------------------------------------
// fp16 1-pass GEMM mainloop: acc = A @ B^T, 128x128 tile, K=1024.
// 3-stage cp.async pipeline, single __syncthreads per iteration.
// ---------------------------------------------------------------------------
#define BK     32
#define PAD    40
#define TILE_B (128 * PAD * 2)          // 10240 B
#define GEMM_SMEM (3 * 2 * TILE_B)      // 61440 B

__device__ __forceinline__ void load_stage1(uint32_t sb, int stg, int kc,
        const __half* __restrict__ Ahi, const __half* __restrict__ Bhi,
        int m0, int n0, int tid) {
    const __half* srcs[2] = {Ahi, Bhi};
    const int r0s[2] = {m0, n0};
    uint32_t base = sb + stg * (2 * TILE_B);
#pragma unroll
    for (int t = 0; t < 2; t++) {
        const __half* src = srcs[t];
        const int r0 = r0s[t];
        uint32_t tb = base + t * TILE_B;
#pragma unroll
        for (int it = 0; it < 2; it++) {
            int seg = it * 256 + tid;
            int r = seg >> 2, c8 = (seg & 3) * 8;
            cp16(tb + (r * PAD + c8) * 2,
                 src + (size_t)(r0 + r) * 1024 + kc * BK + c8);
        }
    }
}

__device__ __forceinline__ void tc_gemm_mainloop1(
        const __half* __restrict__ Ahi, const __half* __restrict__ Bhi,
        int m0, int n0, float acc[4][4][4]) {
    extern __shared__ char smem[];
    const uint32_t sb = smem_to_u32(smem);
    const int tid = threadIdx.x, lane = tid & 31, warp = tid >> 5;
    const int wm = warp >> 2, wn = warp & 3;

#pragma unroll
    for (int i = 0; i < 4; i++)
#pragma unroll
        for (int j = 0; j < 4; j++)
#pragma unroll
            for (int e = 0; e < 4; e++) acc[i][j][e] = 0.f;

    load_stage1(sb, 0, 0, Ahi, Bhi, m0, n0, tid);
    CP_COMMIT();
    load_stage1(sb, 1, 1, Ahi, Bhi, m0, n0, tid);
    CP_COMMIT();

    const uint32_t aoff = (uint32_t)(((wm * 64 + (lane & 15)) * PAD + (lane >> 4) * 8) * 2);
    const uint32_t boff = (uint32_t)(((wn * 32 + (lane & 7) + ((lane >> 4) << 3)) * PAD
                                      + ((lane >> 3) & 1) * 8) * 2);

    int cur = 0, tgt = 2;   // stage kc%3, load target (kc+2)%3
    for (int kc = 0; kc < 1024 / BK; kc++) {
        CP_WAIT1();
        __syncthreads();
        if (kc + 2 < 1024 / BK)
            load_stage1(sb, tgt, kc + 2, Ahi, Bhi, m0, n0, tid);
        CP_COMMIT();

        const uint32_t aB = sb + cur * (2 * TILE_B);
        const uint32_t bB = aB + TILE_B;
#pragma unroll
        for (int ks = 0; ks < 2; ks++) {
            const uint32_t kadd = (uint32_t)(ks * 32);
            uint32_t ahi[4][4];
#pragma unroll
            for (int mt = 0; mt < 4; mt++)
                ldmx4(ahi[mt], aB + aoff + (uint32_t)(mt * 16 * PAD * 2) + kadd);
            uint32_t bhi[2][4];
#pragma unroll
            for (int nt2 = 0; nt2 < 2; nt2++)
                ldmx4(bhi[nt2], bB + boff + (uint32_t)(nt2 * 16 * PAD * 2) + kadd);
#pragma unroll
            for (int mt = 0; mt < 4; mt++)
#pragma unroll
                for (int nt = 0; nt < 4; nt++)
                    mma16816(acc[mt][nt], ahi[mt], &bhi[nt >> 1][(nt & 1) * 2]);
        }
        cur = (cur == 2) ? 0 : cur + 1;
        tgt = (tgt == 2) ? 0 : tgt + 1;
    }
}

// ---------------------------------------------------------------------------
// QKV GEMM with fused RoPE + fp16 epilogue.
// ---------------------------------------------------------------------------
__global__ void __launch_bounds__(256, 2) tc_gemm_qkv(
        const int* __restrict__ tok, const int* __restrict__ use_rope,
        const float* __restrict__ cs, const float* __restrict__ sn) {
    const int z = blockIdx.z;
    const __half* bhi = (z == 0) ? g_wqhi : (z == 1) ? g_wkhi : g_wvhi;
    const int m0 = blockIdx.y * 128, n0 = blockIdx.x * 128;

    float acc[4][4][4];
    tc_gemm_mainloop1(g_xhi, bhi, m0, n0, acc);

    const int lane = threadIdx.x & 31, warp = threadIdx.x >> 5;
    const int wm = warp >> 2, wn = warp & 3;
    const int erow = lane >> 2, ecol = (lane & 3) * 2;
    const int ur = (z < 2) ? use_rope[0] : 0;

    unsigned short* dhi = (z == 0) ? (unsigned short*)g_qhi :
                          (z == 1) ? (unsigned short*)g_khi : (unsigned short*)g_vhi;

#pragma unroll
    for (int mt = 0; mt < 4; mt++)
#pragma unroll
        for (int nt = 0; nt < 4; nt++) {
            const int c0 = n0 + wn * 32 + nt * 8 + ecol;
            const int j = (c0 & 63) >> 1;
#pragma unroll
            for (int hf = 0; hf < 2; hf++) {
                const int r = m0 + wm * 64 + mt * 16 + erow + hf * 8;
                float v0 = acc[mt][nt][hf * 2];
                float v1 = acc[mt][nt][hf * 2 + 1];
                float rx = v0, ry = v1;
                if (ur) {
                    int pos = tok[r & (S_ - 1)];
                    float c  = cs[pos * 32 + j];
                    float si = sn[pos * 32 + j];
                    rx = v0 * c - v1 * si;
                    ry = v1 * c + v0 * si;
                }
                *(ushort2*)(dhi + (size_t)r * 1024 + c0) = make_ushort2(h16u(rx), h16u(ry));
            }
        }
}

// ---------------------------------------------------------------------------
// Output GEMM: fp32 epilogue to d_out.
// ---------------------------------------------------------------------------
__global__ void __launch_bounds__(256, 2) tc_gemm_out(float* __restrict__ out) {
    const int m0 = blockIdx.y * 128, n0 = blockIdx.x * 128;
    float acc[4][4][4];
    tc_gemm_mainloop1(g_yhi, g_wohi, m0, n0, acc);

    const int lane = threadIdx.x & 31, warp = threadIdx.x >> 5;
    const int wm = warp >> 2, wn = warp & 3;
    const int erow = lane >> 2, ecol = (lane & 3) * 2;
#pragma unroll
    for (int mt = 0; mt < 4; mt++)
#pragma unroll
        for (int nt = 0; nt < 4; nt++) {
            size_t r0 = (size_t)(m0 + wm * 64 + mt * 16 + erow);
            int    c0 = n0 + wn * 32 + nt * 8 + ecol;
            *(float2*)(out + r0 * 1024 + c0)       = make_float2(acc[mt][nt][0], acc[mt][nt][1]);
            *(float2*)(out + (r0 + 8) * 1024 + c0) = make_float2(acc[mt][nt][2], acc[mt][nt][3]);
        }
}

// ---------------------------------------------------------------------------
// Flash attention: 1-pass fp16, exp2 softmax, 3-stage KV pipeline,
// single __syncthreads per iteration, deferred l reduction.
// Br=128, Bc=64, d=64, 8 warps.
// ---------------------------------------------------------------------------
#define FPAD   72
#define QT_B   (128 * FPAD * 2)            // 18432 B
#define KV_OFF (QT_B)
#define KVT_B  (64 * FPAD * 2)             // 9216 B
#define FSTG_B (2 * KVT_B)                 // 18432 per stage
#define FLASH_SMEM (KV_OFF + 3 * FSTG_B)   // 73728 B

__device__ __forceinline__ void flash_load_kv(uint32_t sb, int stg, int kt,
                                              int b, int h, int tid) {
    uint32_t base = sb + KV_OFF + stg * FSTG_B;
    size_t krow0 = (size_t)(b * S_ + kt * 64);
    const __half* srcs[2] = {g_khi, g_vhi};
#pragma unroll
    for (int t = 0; t < 2; t++) {
#pragma unroll
        for (int it = 0; it < 2; it++) {
            int seg = it * 256 + tid;
            int r = seg >> 3, c8 = (seg & 7) * 8;
            cp16(base + t * KVT_B + (r * FPAD + c8) * 2,
                 srcs[t] + (krow0 + r) * 1024 + h * HD_ + c8);
        }
    }
}

__global__ void __launch_bounds__(256, 2) flash_mma_kernel() {
    extern __shared__ char fsm[];
    const uint32_t sb = smem_to_u32(fsm);
    const int tid = threadIdx.x, lane = tid & 31, warp = tid >> 5;
    const int qt = gridDim.x - 1 - blockIdx.x;   // heavy tiles first
    const int h = blockIdx.y, b = blockIdx.z;
    const int q0 = qt * 128;
    const size_t qrow0 = (size_t)(b * S_ + q0);
    const int nb = 2 * (qt + 1);

    // prologue: Q + KV0 in group0, KV1 in group1
#pragma unroll
    for (int it = 0; it < 4; it++) {
        int seg = it * 256 + tid;
        int r = seg >> 3, c8 = (seg & 7) * 8;
        cp16(sb + (r * FPAD + c8) * 2,
             g_qhi + (qrow0 + r) * 1024 + h * HD_ + c8);
    }
    flash_load_kv(sb, 0, 0, b, h, tid);
    CP_COMMIT();
    flash_load_kv(sb, 1, 1, b, h, tid);
    CP_COMMIT();

    float oacc[8][4];
#pragma unroll
    for (int nt = 0; nt < 8; nt++)
#pragma unroll
        for (int e = 0; e < 4; e++) oacc[nt][e] = 0.f;
    float m_i[2] = {-1e30f, -1e30f}, l_i[2] = {0.f, 0.f};   // l_i lane-local

    // hoisted ldmatrix address bases
    const int wm16 = warp * 16;
    const uint32_t qbase = sb + (uint32_t)(((wm16 + (lane & 15)) * FPAD + (lane >> 4) * 8) * 2);
    const uint32_t koff  = (uint32_t)((((lane & 7) + ((lane >> 4) << 3)) * FPAD
                                       + ((lane >> 3) & 1) * 8) * 2);
    const int vt = lane >> 3, vi = lane & 7;
    const uint32_t voff  = (uint32_t)((((vt & 1) * 8 + vi) * FPAD + (vt >> 1) * 8) * 2);

    int cur = 0, tgt = 2;
    for (int kt = 0; kt < nb; kt++) {
        CP_WAIT1();
        __syncthreads();
        if (kt + 2 < nb)
            flash_load_kv(sb, tgt, kt + 2, b, h, tid);
        CP_COMMIT();

        const uint32_t kb = sb + KV_OFF + cur * FSTG_B;

        // ---- S = Q @ K^T (raw scores) ----
        float sacc[8][4];
#pragma unroll
        for (int nt = 0; nt < 8; nt++)
#pragma unroll
            for (int e = 0; e < 4; e++) sacc[nt][e] = 0.f;

#pragma unroll
        for (int ks = 0; ks < 4; ks++) {
            const uint32_t kadd = (uint32_t)(ks * 32);
            uint32_t aqh[4];
            ldmx4(aqh, qbase + kadd);
            uint32_t bkh[4][4];
#pragma unroll
            for (int nt2 = 0; nt2 < 4; nt2++)
                ldmx4(bkh[nt2], kb + koff + (uint32_t)(nt2 * 16 * FPAD * 2) + kadd);
#pragma unroll
            for (int nt = 0; nt < 8; nt++)
                mma16816(sacc[nt], aqh, &bkh[nt >> 1][(nt & 1) * 2]);
        }

        // ---- (diagonal-only) causal mask + row max ----
        const bool need_mask = (kt >= nb - 2);
        const int rbase = q0 + wm16 + (lane >> 2);
        const int cbase = kt * 64 + 2 * (lane & 3);
        float mt[2] = {-1e30f, -1e30f};
        if (need_mask) {
#pragma unroll
            for (int nt = 0; nt < 8; nt++)
#pragma unroll
                for (int e = 0; e < 4; e++) {
                    int col = cbase + nt * 8 + (e & 1);
                    int row = rbase + ((e >> 1) << 3);
                    float sv = sacc[nt][e];
                    if (col > row) sv = -1e30f;
                    sacc[nt][e] = sv;
                    mt[e >> 1] = fmaxf(mt[e >> 1], sv);
                }
        } else {
#pragma unroll
            for (int nt = 0; nt < 8; nt++)
#pragma unroll
                for (int e = 0; e < 4; e++)
                    mt[e >> 1] = fmaxf(mt[e >> 1], sacc[nt][e]);
        }
#pragma unroll
        for (int off = 1; off <= 2; off <<= 1)
#pragma unroll
            for (int rh = 0; rh < 2; rh++)
                mt[rh] = fmaxf(mt[rh], __shfl_xor_sync(0xffffffffu, mt[rh], off));

        float mn[2], alpha[2], mnl[2];
#pragma unroll
        for (int rh = 0; rh < 2; rh++) {
            mn[rh] = fmaxf(m_i[rh], mt[rh]);
            alpha[rh] = exp2f((m_i[rh] - mn[rh]) * L2E8);
            m_i[rh] = mn[rh];
            mnl[rh] = mn[rh] * L2E8;
        }

        // ---- exp2(FMA) in place + lane-local sums (reduction deferred) ----
        float psum[2] = {0.f, 0.f};
#pragma unroll
        for (int nt = 0; nt < 8; nt++)
#pragma unroll
            for (int hf = 0; hf < 2; hf++) {
                float p0 = exp2f(fmaf(sacc[nt][hf * 2],     L2E8, -mnl[hf]));
                float p1 = exp2f(fmaf(sacc[nt][hf * 2 + 1], L2E8, -mnl[hf]));
                psum[hf] += p0 + p1;
                sacc[nt][hf * 2]     = p0;
                sacc[nt][hf * 2 + 1] = p1;
            }
#pragma unroll
        for (int rh = 0; rh < 2; rh++)
            l_i[rh] = l_i[rh] * alpha[rh] + psum[rh];

#pragma unroll
        for (int nt = 0; nt < 8; nt++) {
            oacc[nt][0] *= alpha[0]; oacc[nt][1] *= alpha[0];
            oacc[nt][2] *= alpha[1]; oacc[nt][3] *= alpha[1];
        }

        // ---- O += P @ V ----
#pragma unroll
        for (int ks = 0; ks < 4; ks++) {
            const float* s0 = sacc[2 * ks];
            const float* s1 = sacc[2 * ks + 1];
            uint32_t pah[4];
            pah[0] = pack2(s0[0], s0[1]); pah[1] = pack2(s0[2], s0[3]);
            pah[2] = pack2(s1[0], s1[1]); pah[3] = pack2(s1[2], s1[3]);
            const uint32_t vks = kb + KVT_B + voff + (uint32_t)(ks * 16 * FPAD * 2);
#pragma unroll
            for (int ntp = 0; ntp < 4; ntp++) {
                uint32_t vh[4];
                ldmx4t(vh, vks + (uint32_t)(ntp * 32));
                mma16816(oacc[2*ntp],   pah, &vh[0]);
                mma16816(oacc[2*ntp+1], pah, &vh[2]);
            }
        }

        cur = (cur == 2) ? 0 : cur + 1;
        tgt = (tgt == 2) ? 0 : tgt + 1;
    }

    // ---- deferred l reduction + epilogue ----
#pragma unroll
    for (int off = 1; off <= 2; off <<= 1)
#pragma unroll
        for (int rh = 0; rh < 2; rh++)
            l_i[rh] += __shfl_xor_sync(0xffffffffu, l_i[rh], off);

    float inv0 = 1.f / l_i[0], inv1 = 1.f / l_i[1];
    size_t row0 = qrow0 + wm16 + (lane >> 2);
    int colb = h * HD_ + 2 * (lane & 3);
    unsigned short* yh = (unsigned short*)g_yhi;
#pragma unroll
    for (int nt = 0; nt < 8; nt++) {
        int col = colb + nt * 8;
        *(ushort2*)(yh + row0 * 1024 + col) =
            make_ushort2(h16u(oacc[nt][0] * inv0), h16u(oacc[nt][1] * inv0));
        *(ushort2*)(yh + (row0 + 8) * 1024 + col) =
            make_ushort2(h16u(oacc[nt][2] * inv1), h16u(oacc[nt][3] * inv1));
    }
}

// ---------------------------------------------------------------------------
extern "C" void kernel_launch(void* const* d_in, const int* in_sizes, int n_in,
                              void* d_out, int out_size) {
    const float* x        = (const float*)d_in[0];
    const int*   tok      = (const int*)  d_in[1];
    const int*   use_rope = (const int*)  d_in[2];
    const float* Wq       = (const float*)d_in[3];
    const float* Wk       = (const float*)d_in[4];
    const float* Wv       = (const float*)d_in[5];
    const float* Wo       = (const float*)d_in[6];
    const float* cs       = (const float*)d_in[7];
    const float* sn       = (const float*)d_in[8];
    float* out = (float*)d_out;

    void *p_xhi;
    cudaGetSymbolAddress(&p_xhi, g_xhi);

    cudaFuncSetAttribute(tc_gemm_qkv, cudaFuncAttributeMaxDynamicSharedMemorySize, GEMM_SMEM);
    cudaFuncSetAttribute(tc_gemm_out, cudaFuncAttributeMaxDynamicSharedMemorySize, GEMM_SMEM);
    cudaFuncSetAttribute(flash_mma_kernel, cudaFuncAttributeMaxDynamicSharedMemorySize, FLASH_SMEM);

    const int nx4 = (B_*S_*D_) / 4;
    const int nw4 = (D_*D_) / 4;

    split1_kernel<<<(nx4 + 255) / 256, 256>>>(x, (__half*)p_xhi, nx4);
    split1w_kernel<<<dim3((nw4 + 255) / 256, 4), 256>>>(Wq, Wk, Wv, Wo, nw4);

    tc_gemm_qkv<<<dim3(8, 32, 3), 256, GEMM_SMEM>>>(tok, use_rope, cs, sn);

    flash_mma_kernel<<<dim3(S_ / 128, H_, B_), 256, FLASH_SMEM>>>();

    tc_gemm_out<<<dim3(8, 32), 256, GEMM_SMEM>>>(out);
}